// round 10
// baseline (speedup 1.0000x reference)
#include <cuda_runtime.h>
#include <cuda_bf16.h>
#include <math.h>

// ---------------------------------------------------------------------------
// Problem constants
// ---------------------------------------------------------------------------
#define S 2048
#define HIDDEN 2048
#define Q_LORA 1536
#define KV_LORA 512
#define NOPE 128
#define ROPE 64
#define V_DIM 128
#define NH 16
#define QK 192          // NOPE + ROPE
#define KVD 256         // NOPE + V_DIM
#define EPSV 1e-6f

// ---------------------------------------------------------------------------
// Scratch (static device globals)
// ---------------------------------------------------------------------------
__device__ float g_qc    [(size_t)S * Q_LORA];
__device__ float g_q     [(size_t)S * NH * QK];
__device__ float g_kvc   [(size_t)S * (KV_LORA + ROPE)];
__device__ float g_kvlat [(size_t)S * KV_LORA];
__device__ float g_kv    [(size_t)S * NH * KVD];
__device__ float g_krope [(size_t)S * ROPE];
__device__ float g_attn  [(size_t)S * NH * V_DIM];

// tf32-rounded copies of external inputs (weights + hidden)
__device__ float g_hid_r [(size_t)S * HIDDEN];
__device__ float g_wqa_r [(size_t)HIDDEN * Q_LORA];
__device__ float g_wqb_r [(size_t)Q_LORA * NH * QK];
__device__ float g_wkva_r[(size_t)HIDDEN * (KV_LORA + ROPE)];
__device__ float g_wkvb_r[(size_t)KV_LORA * NH * KVD];
__device__ float g_wo_r  [(size_t)NH * V_DIM * HIDDEN];

// ---------------------------------------------------------------------------
// tf32 helpers
// ---------------------------------------------------------------------------
__device__ __forceinline__ unsigned cvt_tf32(float x) {
    unsigned r;
    asm("cvt.rna.tf32.f32 %0, %1;" : "=r"(r) : "f"(x));
    return r;
}
__device__ __forceinline__ float round_tf32(float x) {
    return __uint_as_float(cvt_tf32(x));
}

__device__ __forceinline__ void cp_async16(float* dst, const float* src, bool pred) {
    unsigned d = (unsigned)__cvta_generic_to_shared(dst);
    int sz = pred ? 16 : 0;
    asm volatile("cp.async.cg.shared.global [%0], [%1], 16, %2;"
                 :: "r"(d), "l"(src), "r"(sz));
}

#define CP_COMMIT() asm volatile("cp.async.commit_group;")
#define CP_WAIT0()  asm volatile("cp.async.wait_group 0;")
#define CP_WAIT1()  asm volatile("cp.async.wait_group 1;")

#define MMA_TF32(d, a, b)                                                     \
    asm volatile(                                                             \
        "mma.sync.aligned.m16n8k8.row.col.f32.tf32.tf32.f32 "                 \
        "{%0,%1,%2,%3},{%4,%5,%6,%7},{%8,%9},{%0,%1,%2,%3};"                  \
        : "+f"((d)[0]), "+f"((d)[1]), "+f"((d)[2]), "+f"((d)[3])              \
        : "r"((a)[0]), "r"((a)[1]), "r"((a)[2]), "r"((a)[3]),                 \
          "r"((b)[0]), "r"((b)[1]))

// ---------------------------------------------------------------------------
// tf32 tensor-core GEMM: C[M,N] = alpha * A[M,K] @ B, row-major.
// Inputs MUST already be tf32-rounded (no cvt in the inner loop).
// ROUND_OUT: round outputs to tf32 (for tensors feeding later GEMMs)
// CTA tile 128 x BNv x 32, 256 threads = 8 warps (4m x 2n),
// warp tile 32 x (BNv/2). 3-stage cp.async pipeline, 2 CTAs/SM.
// ---------------------------------------------------------------------------
#define BM 128
#define BK 32
#define AST 36                   // smem stride for A tiles
#define ASTG (BM * AST)          // 4608 floats per A stage
#define NSTAGE 3

template <int BNv, bool ROUND_OUT>
__global__ __launch_bounds__(256, 2) void mma_gemm(
    const float* __restrict__ A, int lda,
    const float* __restrict__ B, int ldb,
    float* __restrict__ C, int ldc,
    int M, int N, int K, float alpha)
{
    constexpr int NT   = BNv / 16;                 // n-tiles per warp
    constexpr int BST  = BNv + 8;                  // k-major B smem stride
    constexpr int BSTG = BK * BST;

    const int bm = blockIdx.y * BM;
    const int bn = blockIdx.x * BNv;

    const int niter = K / BK;

    extern __shared__ float smem[];
    float* As = smem;                     // [NSTAGE][ASTG]
    float* Bs = smem + NSTAGE * ASTG;     // [NSTAGE][BSTG]

    const int tid  = threadIdx.x;
    const int lane = tid & 31;
    const int wid  = tid >> 5;
    const int wm   = wid & 3;             // warp row block (32 rows)
    const int wn   = wid >> 2;            // warp col block (BNv/2 cols)

    float acc[2][NT][4];
#pragma unroll
    for (int mt = 0; mt < 2; mt++)
#pragma unroll
        for (int nt = 0; nt < NT; nt++)
#pragma unroll
            for (int i = 0; i < 4; i++) acc[mt][nt][i] = 0.f;

    auto load_A = [&](int stage, int k0) {
#pragma unroll
        for (int p = 0; p < 4; p++) {
            int lin = p * 256 + tid;
            int r = lin >> 3, cq = lin & 7;
            cp_async16(As + stage * ASTG + r * AST + cq * 4,
                       A + (long long)(bm + r) * lda + k0 + cq * 4, true);
        }
    };
    auto load_B = [&](int stage, int k0) {
#pragma unroll
        for (int p = 0; p < (BNv + 31) / 32; p++) {
            int lin = p * 256 + tid;
            if (BNv >= 32 * ((BNv + 31) / 32) || lin < BK * (BNv / 4)) {
                int r = lin / (BNv / 4);
                int cq = lin % (BNv / 4);
                bool pred = (bn + cq * 4) < N;
                cp_async16(Bs + stage * BSTG + r * BST + cq * 4,
                           B + (long long)(k0 + r) * ldb + bn + cq * 4, pred);
            }
        }
    };

    // ---- pipeline prologue: stages 0 and 1 in flight ----
    load_A(0, 0); load_B(0, 0); CP_COMMIT();
    if (niter > 1) { load_A(1, BK); load_B(1, BK); CP_COMMIT(); }

    // ---- main loop ----
    for (int it = 0; it < niter; it++) {
        if (it + 1 < niter) CP_WAIT1(); else CP_WAIT0();
        __syncthreads();

        if (it + 2 < niter) {
            int stg = (it + 2) % NSTAGE;
            load_A(stg, (it + 2) * BK);
            load_B(stg, (it + 2) * BK);
            CP_COMMIT();
        }

        const int cur = it % NSTAGE;
        const float* Asb = As + cur * ASTG;
        const float* Bsb = Bs + cur * BSTG;

#pragma unroll
        for (int ks = 0; ks < BK / 8; ks++) {
            const int kq = ks * 8 + (lane & 3);
            unsigned af[2][4];
#pragma unroll
            for (int mt = 0; mt < 2; mt++) {
                int m0 = wm * 32 + mt * 16 + (lane >> 2);
                af[mt][0] = __float_as_uint(Asb[m0 * AST + kq]);
                af[mt][1] = __float_as_uint(Asb[(m0 + 8) * AST + kq]);
                af[mt][2] = __float_as_uint(Asb[m0 * AST + kq + 4]);
                af[mt][3] = __float_as_uint(Asb[(m0 + 8) * AST + kq + 4]);
            }
            unsigned bf[NT][2];
#pragma unroll
            for (int nt = 0; nt < NT; nt++) {
                int n0 = wn * (BNv / 2) + nt * 8 + (lane >> 2);
                bf[nt][0] = __float_as_uint(Bsb[kq * BST + n0]);
                bf[nt][1] = __float_as_uint(Bsb[(kq + 4) * BST + n0]);
            }
#pragma unroll
            for (int mt = 0; mt < 2; mt++)
#pragma unroll
                for (int nt = 0; nt < NT; nt++)
                    MMA_TF32(acc[mt][nt], af[mt], bf[nt]);
        }
    }

    // ---- epilogue ----
#pragma unroll
    for (int mt = 0; mt < 2; mt++) {
        int r0 = bm + wm * 32 + mt * 16 + (lane >> 2);
#pragma unroll
        for (int nt = 0; nt < NT; nt++) {
            int c0 = bn + wn * (BNv / 2) + nt * 8 + (lane & 3) * 2;
            if (c0 < N) {
                float x0 = acc[mt][nt][0] * alpha, x1 = acc[mt][nt][1] * alpha;
                float x2 = acc[mt][nt][2] * alpha, x3 = acc[mt][nt][3] * alpha;
                if (ROUND_OUT) {
                    x0 = round_tf32(x0); x1 = round_tf32(x1);
                    x2 = round_tf32(x2); x3 = round_tf32(x3);
                }
                *reinterpret_cast<float2*>(C + (long long)r0 * ldc + c0) =
                    make_float2(x0, x1);
                *reinterpret_cast<float2*>(C + (long long)(r0 + 8) * ldc + c0) =
                    make_float2(x2, x3);
            }
        }
    }
}

// ---------------------------------------------------------------------------
// Fused causal flash attention (tf32 mma, online softmax).
// Grid (16 q-tiles, 16 heads), 256 threads = 8 warps, each warp owns 16 rows.
// Q fragments are register-resident (loaded once; Q never changes across
// k-tiles), cutting S-phase LDS by 20%.
// smem: Q 128x192(s196) | K 64x192(s196) | V 64x128(s136) | P 128x64(s68)
// ---------------------------------------------------------------------------
#define QST 196
#define KST 196
#define VST 136
#define PST 68
#define FL_Q 0
#define FL_K 25088
#define FL_V 37632
#define FL_P 46336
#define FLASH_SMEM ((46336 + 128 * PST) * 4)   // 220,160 bytes
#define NEGINF (-3.0e38f)

__global__ __launch_bounds__(256) void flash_attn_kernel(
    const float* __restrict__ q,
    const float* __restrict__ kv,
    const float* __restrict__ krope,
    float* __restrict__ attn)
{
    const int qt  = (int)gridDim.x - 1 - (int)blockIdx.x;  // heavy tiles first
    const int h   = blockIdx.y;
    const int bm  = qt * 128;
    const int nkt = bm / 64 + 2;
    const float scale = 0.07216878364870322f;  // 1/sqrt(192)

    extern __shared__ float sm[];
    float* Qs = sm + FL_Q;
    float* Ks = sm + FL_K;
    float* Vs = sm + FL_V;
    float* Ps = sm + FL_P;

    const int tid  = threadIdx.x;
    const int lane = tid & 31;
    const int wid  = tid >> 5;
    const int qr   = lane >> 2;
    const int qc   = lane & 3;
    const int row0 = wid * 16 + qr;        // this thread's base row in tile

    auto load_K = [&](int kt) {
        int t0 = kt * 64;
#pragma unroll
        for (int p = 0; p < 12; p++) {
            int lin = p * 256 + tid;
            int r = lin / 48, seg = lin % 48;
            const float* src = (seg < 32)
                ? kv + ((long long)(t0 + r) * NH + h) * KVD + seg * 4
                : krope + (long long)(t0 + r) * ROPE + (seg - 32) * 4;
            cp_async16(Ks + r * KST + seg * 4, src, true);
        }
    };
    auto load_V = [&](int kt) {
        int t0 = kt * 64;
#pragma unroll
        for (int p = 0; p < 8; p++) {
            int lin = p * 256 + tid;
            int r = lin / 32, c = lin % 32;
            cp_async16(Vs + r * VST + c * 4,
                       kv + ((long long)(t0 + r) * NH + h) * KVD + NOPE + c * 4,
                       true);
        }
    };

    // ---- prologue: Q tile + first K/V tile ----
#pragma unroll
    for (int p = 0; p < 24; p++) {
        int lin = p * 256 + tid;
        int r = lin / 48, seg = lin % 48;
        cp_async16(Qs + r * QST + seg * 4,
                   q + ((long long)(bm + r) * NH + h) * QK + seg * 4, true);
    }
    load_K(0);
    load_V(0);
    CP_COMMIT();
    CP_WAIT0();
    __syncthreads();

    // ---- register-resident Q fragments (loaded once) ----
    unsigned qf[24][4];
#pragma unroll
    for (int ks = 0; ks < 24; ks++) {
        int kq = ks * 8 + qc;
        qf[ks][0] = __float_as_uint(Qs[row0 * QST + kq]);
        qf[ks][1] = __float_as_uint(Qs[(row0 + 8) * QST + kq]);
        qf[ks][2] = __float_as_uint(Qs[row0 * QST + kq + 4]);
        qf[ks][3] = __float_as_uint(Qs[(row0 + 8) * QST + kq + 4]);
    }

    float o[16][4];
#pragma unroll
    for (int nt = 0; nt < 16; nt++)
#pragma unroll
        for (int i = 0; i < 4; i++) o[nt][i] = 0.f;
    float mA = NEGINF, mB = NEGINF, lA = 0.f, lB = 0.f;

    for (int kt = 0; kt < nkt; kt++) {
        const int t0 = kt * 64;

        // ---- S = Q K^T (16x64 per warp, K=192) ----
        float sacc[8][4];
#pragma unroll
        for (int nt = 0; nt < 8; nt++)
#pragma unroll
            for (int i = 0; i < 4; i++) sacc[nt][i] = 0.f;

#pragma unroll
        for (int ks = 0; ks < 24; ks++) {
            const int kq = ks * 8 + qc;
            unsigned bf[8][2];
#pragma unroll
            for (int nt = 0; nt < 8; nt++) {
                int n0 = nt * 8 + qr;
                bf[nt][0] = __float_as_uint(Ks[n0 * KST + kq]);
                bf[nt][1] = __float_as_uint(Ks[n0 * KST + kq + 4]);
            }
#pragma unroll
            for (int nt = 0; nt < 8; nt++)
                MMA_TF32(sacc[nt], qf[ks], bf[nt]);
        }

        // ---- scale + causal mask + tile row-max ----
        const int rowA = bm + row0;
        const int rowB = rowA + 8;
        float tmA = NEGINF, tmB = NEGINF;
#pragma unroll
        for (int nt = 0; nt < 8; nt++) {
            int c0 = t0 + nt * 8 + qc * 2;
            float v0 = (c0     <= rowA) ? sacc[nt][0] * scale : NEGINF;
            float v1 = (c0 + 1 <= rowA) ? sacc[nt][1] * scale : NEGINF;
            float v2 = (c0     <= rowB) ? sacc[nt][2] * scale : NEGINF;
            float v3 = (c0 + 1 <= rowB) ? sacc[nt][3] * scale : NEGINF;
            sacc[nt][0] = v0; sacc[nt][1] = v1;
            sacc[nt][2] = v2; sacc[nt][3] = v3;
            tmA = fmaxf(tmA, fmaxf(v0, v1));
            tmB = fmaxf(tmB, fmaxf(v2, v3));
        }
        tmA = fmaxf(tmA, __shfl_xor_sync(0xffffffffu, tmA, 1));
        tmA = fmaxf(tmA, __shfl_xor_sync(0xffffffffu, tmA, 2));
        tmB = fmaxf(tmB, __shfl_xor_sync(0xffffffffu, tmB, 1));
        tmB = fmaxf(tmB, __shfl_xor_sync(0xffffffffu, tmB, 2));

        const float mA2 = fmaxf(mA, tmA);
        const float mB2 = fmaxf(mB, tmB);
        const float aA = __expf(mA - mA2);
        const float aB = __expf(mB - mB2);

        // ---- P = exp(S - m), rounded tf32; accumulate row sums ----
        float sA = 0.f, sB = 0.f;
#pragma unroll
        for (int nt = 0; nt < 8; nt++) {
            float p0 = round_tf32(__expf(sacc[nt][0] - mA2));
            float p1 = round_tf32(__expf(sacc[nt][1] - mA2));
            float p2 = round_tf32(__expf(sacc[nt][2] - mB2));
            float p3 = round_tf32(__expf(sacc[nt][3] - mB2));
            sA += p0 + p1;
            sB += p2 + p3;
            int c = nt * 8 + qc * 2;
            *reinterpret_cast<float2*>(Ps + row0 * PST + c) = make_float2(p0, p1);
            *reinterpret_cast<float2*>(Ps + (row0 + 8) * PST + c) = make_float2(p2, p3);
        }
        sA += __shfl_xor_sync(0xffffffffu, sA, 1);
        sA += __shfl_xor_sync(0xffffffffu, sA, 2);
        sB += __shfl_xor_sync(0xffffffffu, sB, 1);
        sB += __shfl_xor_sync(0xffffffffu, sB, 2);

        lA = lA * aA + sA;
        lB = lB * aB + sB;
        mA = mA2;
        mB = mB2;
#pragma unroll
        for (int nt = 0; nt < 16; nt++) {
            o[nt][0] *= aA; o[nt][1] *= aA;
            o[nt][2] *= aB; o[nt][3] *= aB;
        }

        __syncthreads();   // all warps done with Ks, Ps written

        // prefetch next K while PV runs (K buffer is free now)
        if (kt + 1 < nkt) { load_K(kt + 1); CP_COMMIT(); }

        // ---- O += P @ V (16x128 per warp, K=64) ----
#pragma unroll
        for (int ks = 0; ks < 8; ks++) {
            const int kq = ks * 8 + qc;
            unsigned af[4];
            af[0] = __float_as_uint(Ps[row0 * PST + kq]);
            af[1] = __float_as_uint(Ps[(row0 + 8) * PST + kq]);
            af[2] = __float_as_uint(Ps[row0 * PST + kq + 4]);
            af[3] = __float_as_uint(Ps[(row0 + 8) * PST + kq + 4]);
#pragma unroll
            for (int nt = 0; nt < 16; nt++) {
                unsigned bf[2];
                int n0 = nt * 8 + qr;
                bf[0] = __float_as_uint(Vs[kq * VST + n0]);
                bf[1] = __float_as_uint(Vs[(kq + 4) * VST + n0]);
                MMA_TF32(o[nt], af, bf);
            }
        }

        __syncthreads();   // all warps done with Vs, Ps

        if (kt + 1 < nkt) {
            load_V(kt + 1);
            CP_COMMIT();
            CP_WAIT0();
            __syncthreads();   // next K/V visible to all
        }
    }

    // ---- epilogue: O / l, rounded tf32 ----
    const float invA = 1.f / lA;
    const float invB = 1.f / lB;
    const long long baseA = ((long long)(bm + row0) * NH + h) * V_DIM;
    const long long baseB = ((long long)(bm + row0 + 8) * NH + h) * V_DIM;
#pragma unroll
    for (int nt = 0; nt < 16; nt++) {
        int c = nt * 8 + qc * 2;
        *reinterpret_cast<float2*>(attn + baseA + c) =
            make_float2(round_tf32(o[nt][0] * invA), round_tf32(o[nt][1] * invA));
        *reinterpret_cast<float2*>(attn + baseB + c) =
            make_float2(round_tf32(o[nt][2] * invB), round_tf32(o[nt][3] * invB));
    }
}

// ---------------------------------------------------------------------------
// Batched tf32 pre-rounding copy: all 6 tensors in ONE launch.
// Each block handles exactly one 1024-float4 (16 KB) chunk; every segment's
// n4 is a multiple of 1024.
// ---------------------------------------------------------------------------
struct CopyArgs {
    const float4* src[6];
    float4*       dst[6];
    int           prefix[7];   // chunk-index prefix sums
};

__global__ __launch_bounds__(256) void round_copy_all_kernel(CopyArgs a)
{
    const int b = blockIdx.x;
    int s = 0;
#pragma unroll
    for (int i = 1; i < 6; i++)
        if (b >= a.prefix[i]) s = i;
    const int chunk = b - a.prefix[s];
    const float4* in  = a.src[s] + (long long)chunk * 1024;
    float4*       out = a.dst[s] + (long long)chunk * 1024;

    const int i0 = threadIdx.x;
    float4 x = in[i0];
    float4 y = in[i0 + 256];
    float4 z = in[i0 + 512];
    float4 w = in[i0 + 768];
    x.x = round_tf32(x.x); x.y = round_tf32(x.y);
    x.z = round_tf32(x.z); x.w = round_tf32(x.w);
    y.x = round_tf32(y.x); y.y = round_tf32(y.y);
    y.z = round_tf32(y.z); y.w = round_tf32(y.w);
    z.x = round_tf32(z.x); z.y = round_tf32(z.y);
    z.z = round_tf32(z.z); z.w = round_tf32(z.w);
    w.x = round_tf32(w.x); w.y = round_tf32(w.y);
    w.z = round_tf32(w.z); w.w = round_tf32(w.w);
    out[i0]       = x;
    out[i0 + 256] = y;
    out[i0 + 512] = z;
    out[i0 + 768] = w;
}

// ---------------------------------------------------------------------------
// RMSNorm: one block per row; output rounded to tf32
// ---------------------------------------------------------------------------
__global__ __launch_bounds__(256) void rmsnorm_kernel(
    const float* __restrict__ in, int ldin,
    float* __restrict__ out, int ldout,
    const float* __restrict__ w, int cols)
{
    const int r = blockIdx.x;
    const float* x = in + (long long)r * ldin;
    float ss = 0.f;
    for (int c = threadIdx.x; c < cols; c += blockDim.x) {
        float v = x[c];
        ss += v * v;
    }
    __shared__ float sh[256];
    sh[threadIdx.x] = ss;
    __syncthreads();
    for (int s = 128; s > 0; s >>= 1) {
        if (threadIdx.x < s) sh[threadIdx.x] += sh[threadIdx.x + s];
        __syncthreads();
    }
    float scale = rsqrtf(sh[0] / (float)cols + EPSV);
    for (int c = threadIdx.x; c < cols; c += blockDim.x)
        out[(long long)r * ldout + c] = round_tf32(x[c] * scale * w[c]);
}

// ---------------------------------------------------------------------------
// RoPE (interleaved): rotates q rope dims (rounded), emits rounded k_rope.
// q nope dims are already tf32 (GEMM3 ROUND_OUT).
// ---------------------------------------------------------------------------
__global__ __launch_bounds__(512) void rope_kernel(
    float* __restrict__ q, const float* __restrict__ kvc,
    float* __restrict__ krope, const int* __restrict__ positions)
{
    const int s = blockIdx.x;
    const int t = threadIdx.x;
    const int h = t >> 5;
    const int i = t & 31;

    float pos = (float)positions[s];
    float inv = powf(10000.0f, -(2.0f * (float)i) / (float)ROPE);
    float ang = pos * inv;
    float sn, cs;
    sincosf(ang, &sn, &cs);

    float* qp = q + ((long long)s * NH + h) * QK + NOPE + 2 * i;
    float x1 = qp[0], x2 = qp[1];
    qp[0] = round_tf32(x1 * cs - x2 * sn);
    qp[1] = round_tf32(x2 * cs + x1 * sn);

    if (h == 0) {
        const float* kp = kvc + (long long)s * (KV_LORA + ROPE) + KV_LORA + 2 * i;
        float y1 = kp[0], y2 = kp[1];
        krope[(long long)s * ROPE + 2 * i]     = round_tf32(y1 * cs - y2 * sn);
        krope[(long long)s * ROPE + 2 * i + 1] = round_tf32(y2 * cs + y1 * sn);
    }
}

// ---------------------------------------------------------------------------
// Host launcher
// ---------------------------------------------------------------------------
static inline void* sym_addr(const void* symbol)
{
    void* p = nullptr;
    cudaGetSymbolAddress(&p, symbol);
    return p;
}

extern "C" void kernel_launch(void* const* d_in, const int* in_sizes, int n_in,
                              void* d_out, int out_size)
{
    const float* hidden  = (const float*)d_in[0];
    const float* w_qa    = (const float*)d_in[1];
    const float* qa_ln_w = (const float*)d_in[2];
    const float* w_qb    = (const float*)d_in[3];
    const float* w_kva   = (const float*)d_in[4];
    const float* kva_ln_w= (const float*)d_in[5];
    const float* w_kvb   = (const float*)d_in[6];
    const float* w_o     = (const float*)d_in[7];
    const int*   positions = (const int*)d_in[8];
    float* out = (float*)d_out;

    float* qc     = (float*)sym_addr(g_qc);
    float* q      = (float*)sym_addr(g_q);
    float* kvc    = (float*)sym_addr(g_kvc);
    float* kvlat  = (float*)sym_addr(g_kvlat);
    float* kv     = (float*)sym_addr(g_kv);
    float* krope  = (float*)sym_addr(g_krope);
    float* attn   = (float*)sym_addr(g_attn);

    float* hid_r  = (float*)sym_addr(g_hid_r);
    float* wqa_r  = (float*)sym_addr(g_wqa_r);
    float* wqb_r  = (float*)sym_addr(g_wqb_r);
    float* wkva_r = (float*)sym_addr(g_wkva_r);
    float* wkvb_r = (float*)sym_addr(g_wkvb_r);
    float* wo_r   = (float*)sym_addr(g_wo_r);

    const dim3 blk(256);

    const size_t smem_nn128 = (size_t)NSTAGE * (ASTG + BK * (128 + 8)) * 4; // 107,520
    const size_t smem_nn64  = (size_t)NSTAGE * (ASTG + BK * (64 + 8))  * 4; //  82,944
    const size_t smem_nn32  = (size_t)NSTAGE * (ASTG + BK * (32 + 8))  * 4; //  70,656

    cudaFuncSetAttribute(mma_gemm<128, false>,
                         cudaFuncAttributeMaxDynamicSharedMemorySize, (int)smem_nn128);
    cudaFuncSetAttribute(mma_gemm<128, true>,
                         cudaFuncAttributeMaxDynamicSharedMemorySize, (int)smem_nn128);
    cudaFuncSetAttribute(mma_gemm<64, false>,
                         cudaFuncAttributeMaxDynamicSharedMemorySize, (int)smem_nn64);
    cudaFuncSetAttribute(mma_gemm<64, true>,
                         cudaFuncAttributeMaxDynamicSharedMemorySize, (int)smem_nn64);
    cudaFuncSetAttribute(mma_gemm<32, false>,
                         cudaFuncAttributeMaxDynamicSharedMemorySize, (int)smem_nn32);
    cudaFuncSetAttribute(flash_attn_kernel,
                         cudaFuncAttributeMaxDynamicSharedMemorySize, FLASH_SMEM);

    // 0. tf32-round external inputs — single batched launch
    {
        CopyArgs a;
        const float* srcs[6] = { hidden, w_qa, w_qb, w_kva, w_kvb, w_o };
        float* dsts[6]       = { hid_r, wqa_r, wqb_r, wkva_r, wkvb_r, wo_r };
        long long ns[6] = {
            (long long)S * HIDDEN,
            (long long)HIDDEN * Q_LORA,
            (long long)Q_LORA * NH * QK,
            (long long)HIDDEN * (KV_LORA + ROPE),
            (long long)KV_LORA * NH * KVD,
            (long long)NH * V_DIM * HIDDEN };
        int pre = 0;
        for (int i = 0; i < 6; i++) {
            a.src[i] = (const float4*)srcs[i];
            a.dst[i] = (float4*)dsts[i];
            a.prefix[i] = pre;
            pre += (int)(ns[i] / 4 / 1024);   // all sizes divisible by 4096
        }
        a.prefix[6] = pre;
        round_copy_all_kernel<<<pre, blk>>>(a);
    }

    // 1. q_c_raw = hidden @ w_qa            [2048,1536] K=2048, BN=64 (fill)
    mma_gemm<64, false><<<dim3(Q_LORA / 64, S / BM, 1), blk, smem_nn64>>>(
        hid_r, HIDDEN, wqa_r, Q_LORA, qc, Q_LORA,
        S, Q_LORA, HIDDEN, 1.0f);

    // 2. rmsnorm(q_c) in place (rounds output)
    rmsnorm_kernel<<<S, blk>>>(qc, Q_LORA, qc, Q_LORA, qa_ln_w, Q_LORA);

    // 3. q = q_c @ w_qb                     [2048,3072] K=1536, BN=64 (fill)
    mma_gemm<64, true><<<dim3((NH * QK) / 64, S / BM, 1), blk, smem_nn64>>>(
        qc, Q_LORA, wqb_r, NH * QK, q, NH * QK,
        S, NH * QK, Q_LORA, 1.0f);

    // 4. kv_c = hidden @ w_kva              [2048,576] K=2048, BN=32 (fill)
    mma_gemm<32, false><<<dim3((KV_LORA + ROPE) / 32, S / BM, 1), blk, smem_nn32>>>(
        hid_r, HIDDEN, wkva_r, KV_LORA + ROPE, kvc, KV_LORA + ROPE,
        S, KV_LORA + ROPE, HIDDEN, 1.0f);

    // 5. kv_lat = rmsnorm(kv_c[:, :512]) (rounds output)
    rmsnorm_kernel<<<S, blk>>>(kvc, KV_LORA + ROPE, kvlat, KV_LORA, kva_ln_w, KV_LORA);

    // 6. kv = kv_lat @ w_kvb                [2048,4096] K=512, BN=128
    mma_gemm<128, true><<<dim3((NH * KVD) / 128, S / BM, 1), blk, smem_nn128>>>(
        kvlat, KV_LORA, wkvb_r, NH * KVD, kv, NH * KVD,
        S, NH * KVD, KV_LORA, 1.0f);

    // 7. RoPE
    rope_kernel<<<S, 512>>>(q, kvc, krope, positions);

    // 8. fused causal flash attention -> attn (tf32-rounded)
    flash_attn_kernel<<<dim3(S / 128, NH), blk, FLASH_SMEM>>>(q, kv, krope, attn);

    // 9. out = attn @ w_o                   [2048,2048] K=2048, BN=128
    mma_gemm<128, false><<<dim3(HIDDEN / 128, S / BM, 1), blk, smem_nn128>>>(
        attn, NH * V_DIM, wo_r, HIDDEN, out, HIDDEN,
        S, HIDDEN, NH * V_DIM, 1.0f);
}

// round 11
// speedup vs baseline: 1.0463x; 1.0463x over previous
#include <cuda_runtime.h>
#include <cuda_bf16.h>
#include <math.h>

// ---------------------------------------------------------------------------
// Problem constants
// ---------------------------------------------------------------------------
#define S 2048
#define HIDDEN 2048
#define Q_LORA 1536
#define KV_LORA 512
#define NOPE 128
#define ROPE 64
#define V_DIM 128
#define NH 16
#define QK 192          // NOPE + ROPE
#define KVD 256         // NOPE + V_DIM
#define EPSV 1e-6f

// ---------------------------------------------------------------------------
// Scratch (static device globals)
// ---------------------------------------------------------------------------
__device__ float g_qc    [(size_t)S * Q_LORA];
__device__ float g_q     [(size_t)S * NH * QK];
__device__ float g_kvc   [(size_t)S * (KV_LORA + ROPE)];
__device__ float g_kvlat [(size_t)S * KV_LORA];
__device__ float g_kv    [(size_t)S * NH * KVD];
__device__ float g_krope [(size_t)S * ROPE];
__device__ float g_attn  [(size_t)S * NH * V_DIM];

// tf32-rounded copies of external inputs (weights + hidden)
__device__ float g_hid_r [(size_t)S * HIDDEN];
__device__ float g_wqa_r [(size_t)HIDDEN * Q_LORA];
__device__ float g_wqb_r [(size_t)Q_LORA * NH * QK];
__device__ float g_wkva_r[(size_t)HIDDEN * (KV_LORA + ROPE)];
__device__ float g_wkvb_r[(size_t)KV_LORA * NH * KVD];
__device__ float g_wo_r  [(size_t)NH * V_DIM * HIDDEN];

// ---------------------------------------------------------------------------
// tf32 helpers
// ---------------------------------------------------------------------------
__device__ __forceinline__ unsigned cvt_tf32(float x) {
    unsigned r;
    asm("cvt.rna.tf32.f32 %0, %1;" : "=r"(r) : "f"(x));
    return r;
}
__device__ __forceinline__ float round_tf32(float x) {
    return __uint_as_float(cvt_tf32(x));
}

__device__ __forceinline__ void cp_async16(float* dst, const float* src, bool pred) {
    unsigned d = (unsigned)__cvta_generic_to_shared(dst);
    int sz = pred ? 16 : 0;
    asm volatile("cp.async.cg.shared.global [%0], [%1], 16, %2;"
                 :: "r"(d), "l"(src), "r"(sz));
}

#define CP_COMMIT() asm volatile("cp.async.commit_group;")
#define CP_WAIT0()  asm volatile("cp.async.wait_group 0;")
#define CP_WAIT1()  asm volatile("cp.async.wait_group 1;")

#define MMA_TF32(d, a, b)                                                     \
    asm volatile(                                                             \
        "mma.sync.aligned.m16n8k8.row.col.f32.tf32.tf32.f32 "                 \
        "{%0,%1,%2,%3},{%4,%5,%6,%7},{%8,%9},{%0,%1,%2,%3};"                  \
        : "+f"((d)[0]), "+f"((d)[1]), "+f"((d)[2]), "+f"((d)[3])              \
        : "r"((a)[0]), "r"((a)[1]), "r"((a)[2]), "r"((a)[3]),                 \
          "r"((b)[0]), "r"((b)[1]))

// ---------------------------------------------------------------------------
// tf32 tensor-core GEMM: C[M,N] = alpha * A[M,K] @ B, row-major.
// Inputs MUST already be tf32-rounded (no cvt in the inner loop).
// ROUND_OUT: round outputs to tf32 (for tensors feeding later GEMMs)
// CTA tile 128 x BNv x 32, 256 threads = 8 warps (4m x 2n),
// warp tile 32 x (BNv/2). 3-stage cp.async pipeline, 2 CTAs/SM.
// NOTE (R10 lesson): BNv=128 for large GEMMs; smaller BN loses more to
// per-CTA efficiency than it gains from wave packing.
// ---------------------------------------------------------------------------
#define BM 128
#define BK 32
#define AST 36                   // smem stride for A tiles
#define ASTG (BM * AST)          // 4608 floats per A stage
#define NSTAGE 3

template <int BNv, bool ROUND_OUT>
__global__ __launch_bounds__(256, 2) void mma_gemm(
    const float* __restrict__ A, int lda,
    const float* __restrict__ B, int ldb,
    float* __restrict__ C, int ldc,
    int M, int N, int K, float alpha)
{
    constexpr int NT   = BNv / 16;                 // n-tiles per warp
    constexpr int BST  = BNv + 8;                  // k-major B smem stride
    constexpr int BSTG = BK * BST;

    const int bm = blockIdx.y * BM;
    const int bn = blockIdx.x * BNv;

    const int niter = K / BK;

    extern __shared__ float smem[];
    float* As = smem;                     // [NSTAGE][ASTG]
    float* Bs = smem + NSTAGE * ASTG;     // [NSTAGE][BSTG]

    const int tid  = threadIdx.x;
    const int lane = tid & 31;
    const int wid  = tid >> 5;
    const int wm   = wid & 3;             // warp row block (32 rows)
    const int wn   = wid >> 2;            // warp col block (BNv/2 cols)

    float acc[2][NT][4];
#pragma unroll
    for (int mt = 0; mt < 2; mt++)
#pragma unroll
        for (int nt = 0; nt < NT; nt++)
#pragma unroll
            for (int i = 0; i < 4; i++) acc[mt][nt][i] = 0.f;

    auto load_A = [&](int stage, int k0) {
#pragma unroll
        for (int p = 0; p < 4; p++) {
            int lin = p * 256 + tid;
            int r = lin >> 3, cq = lin & 7;
            cp_async16(As + stage * ASTG + r * AST + cq * 4,
                       A + (long long)(bm + r) * lda + k0 + cq * 4, true);
        }
    };
    auto load_B = [&](int stage, int k0) {
#pragma unroll
        for (int p = 0; p < BNv / 32; p++) {
            int lin = p * 256 + tid;
            int r = lin / (BNv / 4);
            int cq = lin % (BNv / 4);
            bool pred = (bn + cq * 4) < N;
            cp_async16(Bs + stage * BSTG + r * BST + cq * 4,
                       B + (long long)(k0 + r) * ldb + bn + cq * 4, pred);
        }
    };

    // ---- pipeline prologue: stages 0 and 1 in flight ----
    load_A(0, 0); load_B(0, 0); CP_COMMIT();
    if (niter > 1) { load_A(1, BK); load_B(1, BK); CP_COMMIT(); }

    // ---- main loop ----
    for (int it = 0; it < niter; it++) {
        if (it + 1 < niter) CP_WAIT1(); else CP_WAIT0();
        __syncthreads();

        if (it + 2 < niter) {
            int stg = (it + 2) % NSTAGE;
            load_A(stg, (it + 2) * BK);
            load_B(stg, (it + 2) * BK);
            CP_COMMIT();
        }

        const int cur = it % NSTAGE;
        const float* Asb = As + cur * ASTG;
        const float* Bsb = Bs + cur * BSTG;

#pragma unroll
        for (int ks = 0; ks < BK / 8; ks++) {
            const int kq = ks * 8 + (lane & 3);
            unsigned af[2][4];
#pragma unroll
            for (int mt = 0; mt < 2; mt++) {
                int m0 = wm * 32 + mt * 16 + (lane >> 2);
                af[mt][0] = __float_as_uint(Asb[m0 * AST + kq]);
                af[mt][1] = __float_as_uint(Asb[(m0 + 8) * AST + kq]);
                af[mt][2] = __float_as_uint(Asb[m0 * AST + kq + 4]);
                af[mt][3] = __float_as_uint(Asb[(m0 + 8) * AST + kq + 4]);
            }
            unsigned bf[NT][2];
#pragma unroll
            for (int nt = 0; nt < NT; nt++) {
                int n0 = wn * (BNv / 2) + nt * 8 + (lane >> 2);
                bf[nt][0] = __float_as_uint(Bsb[kq * BST + n0]);
                bf[nt][1] = __float_as_uint(Bsb[(kq + 4) * BST + n0]);
            }
#pragma unroll
            for (int mt = 0; mt < 2; mt++)
#pragma unroll
                for (int nt = 0; nt < NT; nt++)
                    MMA_TF32(acc[mt][nt], af[mt], bf[nt]);
        }
    }

    // ---- epilogue ----
#pragma unroll
    for (int mt = 0; mt < 2; mt++) {
        int r0 = bm + wm * 32 + mt * 16 + (lane >> 2);
#pragma unroll
        for (int nt = 0; nt < NT; nt++) {
            int c0 = bn + wn * (BNv / 2) + nt * 8 + (lane & 3) * 2;
            if (c0 < N) {
                float x0 = acc[mt][nt][0] * alpha, x1 = acc[mt][nt][1] * alpha;
                float x2 = acc[mt][nt][2] * alpha, x3 = acc[mt][nt][3] * alpha;
                if (ROUND_OUT) {
                    x0 = round_tf32(x0); x1 = round_tf32(x1);
                    x2 = round_tf32(x2); x3 = round_tf32(x3);
                }
                *reinterpret_cast<float2*>(C + (long long)r0 * ldc + c0) =
                    make_float2(x0, x1);
                *reinterpret_cast<float2*>(C + (long long)(r0 + 8) * ldc + c0) =
                    make_float2(x2, x3);
            }
        }
    }
}

// ---------------------------------------------------------------------------
// Fused causal flash attention (tf32 mma, online softmax).
// Grid (16 q-tiles, 16 heads), 256 threads = 8 warps, each warp owns 16 rows.
// Q fragments register-resident (loaded once), cutting S-phase LDS by 20%.
// smem: Q 128x192(s196) | K 64x192(s196) | V 64x128(s136) | P 128x64(s68)
// ---------------------------------------------------------------------------
#define QST 196
#define KST 196
#define VST 136
#define PST 68
#define FL_Q 0
#define FL_K 25088
#define FL_V 37632
#define FL_P 46336
#define FLASH_SMEM ((46336 + 128 * PST) * 4)   // 220,160 bytes
#define NEGINF (-3.0e38f)

__global__ __launch_bounds__(256) void flash_attn_kernel(
    const float* __restrict__ q,
    const float* __restrict__ kv,
    const float* __restrict__ krope,
    float* __restrict__ attn)
{
    const int qt  = (int)gridDim.x - 1 - (int)blockIdx.x;  // heavy tiles first
    const int h   = blockIdx.y;
    const int bm  = qt * 128;
    const int nkt = bm / 64 + 2;
    const float scale = 0.07216878364870322f;  // 1/sqrt(192)

    extern __shared__ float sm[];
    float* Qs = sm + FL_Q;
    float* Ks = sm + FL_K;
    float* Vs = sm + FL_V;
    float* Ps = sm + FL_P;

    const int tid  = threadIdx.x;
    const int lane = tid & 31;
    const int wid  = tid >> 5;
    const int qr   = lane >> 2;
    const int qc   = lane & 3;
    const int row0 = wid * 16 + qr;        // this thread's base row in tile

    auto load_K = [&](int kt) {
        int t0 = kt * 64;
#pragma unroll
        for (int p = 0; p < 12; p++) {
            int lin = p * 256 + tid;
            int r = lin / 48, seg = lin % 48;
            const float* src = (seg < 32)
                ? kv + ((long long)(t0 + r) * NH + h) * KVD + seg * 4
                : krope + (long long)(t0 + r) * ROPE + (seg - 32) * 4;
            cp_async16(Ks + r * KST + seg * 4, src, true);
        }
    };
    auto load_V = [&](int kt) {
        int t0 = kt * 64;
#pragma unroll
        for (int p = 0; p < 8; p++) {
            int lin = p * 256 + tid;
            int r = lin / 32, c = lin % 32;
            cp_async16(Vs + r * VST + c * 4,
                       kv + ((long long)(t0 + r) * NH + h) * KVD + NOPE + c * 4,
                       true);
        }
    };

    // ---- prologue: Q tile + first K/V tile ----
#pragma unroll
    for (int p = 0; p < 24; p++) {
        int lin = p * 256 + tid;
        int r = lin / 48, seg = lin % 48;
        cp_async16(Qs + r * QST + seg * 4,
                   q + ((long long)(bm + r) * NH + h) * QK + seg * 4, true);
    }
    load_K(0);
    load_V(0);
    CP_COMMIT();
    CP_WAIT0();
    __syncthreads();

    // ---- register-resident Q fragments (loaded once) ----
    unsigned qf[24][4];
#pragma unroll
    for (int ks = 0; ks < 24; ks++) {
        int kq = ks * 8 + qc;
        qf[ks][0] = __float_as_uint(Qs[row0 * QST + kq]);
        qf[ks][1] = __float_as_uint(Qs[(row0 + 8) * QST + kq]);
        qf[ks][2] = __float_as_uint(Qs[row0 * QST + kq + 4]);
        qf[ks][3] = __float_as_uint(Qs[(row0 + 8) * QST + kq + 4]);
    }

    float o[16][4];
#pragma unroll
    for (int nt = 0; nt < 16; nt++)
#pragma unroll
        for (int i = 0; i < 4; i++) o[nt][i] = 0.f;
    float mA = NEGINF, mB = NEGINF, lA = 0.f, lB = 0.f;

    for (int kt = 0; kt < nkt; kt++) {
        const int t0 = kt * 64;

        // ---- S = Q K^T (16x64 per warp, K=192) ----
        float sacc[8][4];
#pragma unroll
        for (int nt = 0; nt < 8; nt++)
#pragma unroll
            for (int i = 0; i < 4; i++) sacc[nt][i] = 0.f;

#pragma unroll
        for (int ks = 0; ks < 24; ks++) {
            const int kq = ks * 8 + qc;
            unsigned bf[8][2];
#pragma unroll
            for (int nt = 0; nt < 8; nt++) {
                int n0 = nt * 8 + qr;
                bf[nt][0] = __float_as_uint(Ks[n0 * KST + kq]);
                bf[nt][1] = __float_as_uint(Ks[n0 * KST + kq + 4]);
            }
#pragma unroll
            for (int nt = 0; nt < 8; nt++)
                MMA_TF32(sacc[nt], qf[ks], bf[nt]);
        }

        // ---- scale + causal mask + tile row-max ----
        const int rowA = bm + row0;
        const int rowB = rowA + 8;
        float tmA = NEGINF, tmB = NEGINF;
#pragma unroll
        for (int nt = 0; nt < 8; nt++) {
            int c0 = t0 + nt * 8 + qc * 2;
            float v0 = (c0     <= rowA) ? sacc[nt][0] * scale : NEGINF;
            float v1 = (c0 + 1 <= rowA) ? sacc[nt][1] * scale : NEGINF;
            float v2 = (c0     <= rowB) ? sacc[nt][2] * scale : NEGINF;
            float v3 = (c0 + 1 <= rowB) ? sacc[nt][3] * scale : NEGINF;
            sacc[nt][0] = v0; sacc[nt][1] = v1;
            sacc[nt][2] = v2; sacc[nt][3] = v3;
            tmA = fmaxf(tmA, fmaxf(v0, v1));
            tmB = fmaxf(tmB, fmaxf(v2, v3));
        }
        tmA = fmaxf(tmA, __shfl_xor_sync(0xffffffffu, tmA, 1));
        tmA = fmaxf(tmA, __shfl_xor_sync(0xffffffffu, tmA, 2));
        tmB = fmaxf(tmB, __shfl_xor_sync(0xffffffffu, tmB, 1));
        tmB = fmaxf(tmB, __shfl_xor_sync(0xffffffffu, tmB, 2));

        const float mA2 = fmaxf(mA, tmA);
        const float mB2 = fmaxf(mB, tmB);
        const float aA = __expf(mA - mA2);
        const float aB = __expf(mB - mB2);

        // ---- P = exp(S - m), rounded tf32; accumulate row sums ----
        float sA = 0.f, sB = 0.f;
#pragma unroll
        for (int nt = 0; nt < 8; nt++) {
            float p0 = round_tf32(__expf(sacc[nt][0] - mA2));
            float p1 = round_tf32(__expf(sacc[nt][1] - mA2));
            float p2 = round_tf32(__expf(sacc[nt][2] - mB2));
            float p3 = round_tf32(__expf(sacc[nt][3] - mB2));
            sA += p0 + p1;
            sB += p2 + p3;
            int c = nt * 8 + qc * 2;
            *reinterpret_cast<float2*>(Ps + row0 * PST + c) = make_float2(p0, p1);
            *reinterpret_cast<float2*>(Ps + (row0 + 8) * PST + c) = make_float2(p2, p3);
        }
        sA += __shfl_xor_sync(0xffffffffu, sA, 1);
        sA += __shfl_xor_sync(0xffffffffu, sA, 2);
        sB += __shfl_xor_sync(0xffffffffu, sB, 1);
        sB += __shfl_xor_sync(0xffffffffu, sB, 2);

        lA = lA * aA + sA;
        lB = lB * aB + sB;
        mA = mA2;
        mB = mB2;
#pragma unroll
        for (int nt = 0; nt < 16; nt++) {
            o[nt][0] *= aA; o[nt][1] *= aA;
            o[nt][2] *= aB; o[nt][3] *= aB;
        }

        __syncthreads();   // all warps done with Ks, Ps written

        // prefetch next K while PV runs (K buffer is free now)
        if (kt + 1 < nkt) { load_K(kt + 1); CP_COMMIT(); }

        // ---- O += P @ V (16x128 per warp, K=64) ----
#pragma unroll
        for (int ks = 0; ks < 8; ks++) {
            const int kq = ks * 8 + qc;
            unsigned af[4];
            af[0] = __float_as_uint(Ps[row0 * PST + kq]);
            af[1] = __float_as_uint(Ps[(row0 + 8) * PST + kq]);
            af[2] = __float_as_uint(Ps[row0 * PST + kq + 4]);
            af[3] = __float_as_uint(Ps[(row0 + 8) * PST + kq + 4]);
#pragma unroll
            for (int nt = 0; nt < 16; nt++) {
                unsigned bf[2];
                int n0 = nt * 8 + qr;
                bf[0] = __float_as_uint(Vs[kq * VST + n0]);
                bf[1] = __float_as_uint(Vs[(kq + 4) * VST + n0]);
                MMA_TF32(o[nt], af, bf);
            }
        }

        __syncthreads();   // all warps done with Vs, Ps

        if (kt + 1 < nkt) {
            load_V(kt + 1);
            CP_COMMIT();
            CP_WAIT0();
            __syncthreads();   // next K/V visible to all
        }
    }

    // ---- epilogue: O / l, rounded tf32 ----
    const float invA = 1.f / lA;
    const float invB = 1.f / lB;
    const long long baseA = ((long long)(bm + row0) * NH + h) * V_DIM;
    const long long baseB = ((long long)(bm + row0 + 8) * NH + h) * V_DIM;
#pragma unroll
    for (int nt = 0; nt < 16; nt++) {
        int c = nt * 8 + qc * 2;
        *reinterpret_cast<float2*>(attn + baseA + c) =
            make_float2(round_tf32(o[nt][0] * invA), round_tf32(o[nt][1] * invA));
        *reinterpret_cast<float2*>(attn + baseB + c) =
            make_float2(round_tf32(o[nt][2] * invB), round_tf32(o[nt][3] * invB));
    }
}

// ---------------------------------------------------------------------------
// Batched tf32 pre-rounding copy: all 6 tensors in ONE launch.
// Each block handles exactly one 1024-float4 (16 KB) chunk; every segment's
// n4 is a multiple of 1024.
// ---------------------------------------------------------------------------
struct CopyArgs {
    const float4* src[6];
    float4*       dst[6];
    int           prefix[7];   // chunk-index prefix sums
};

__global__ __launch_bounds__(256) void round_copy_all_kernel(CopyArgs a)
{
    const int b = blockIdx.x;
    int s = 0;
#pragma unroll
    for (int i = 1; i < 6; i++)
        if (b >= a.prefix[i]) s = i;
    const int chunk = b - a.prefix[s];
    const float4* in  = a.src[s] + (long long)chunk * 1024;
    float4*       out = a.dst[s] + (long long)chunk * 1024;

    const int i0 = threadIdx.x;
    float4 x = in[i0];
    float4 y = in[i0 + 256];
    float4 z = in[i0 + 512];
    float4 w = in[i0 + 768];
    x.x = round_tf32(x.x); x.y = round_tf32(x.y);
    x.z = round_tf32(x.z); x.w = round_tf32(x.w);
    y.x = round_tf32(y.x); y.y = round_tf32(y.y);
    y.z = round_tf32(y.z); y.w = round_tf32(y.w);
    z.x = round_tf32(z.x); z.y = round_tf32(z.y);
    z.z = round_tf32(z.z); z.w = round_tf32(z.w);
    w.x = round_tf32(w.x); w.y = round_tf32(w.y);
    w.z = round_tf32(w.z); w.w = round_tf32(w.w);
    out[i0]       = x;
    out[i0 + 256] = y;
    out[i0 + 512] = z;
    out[i0 + 768] = w;
}

// ---------------------------------------------------------------------------
// RMSNorm: one block per row; output rounded to tf32
// ---------------------------------------------------------------------------
__global__ __launch_bounds__(256) void rmsnorm_kernel(
    const float* __restrict__ in, int ldin,
    float* __restrict__ out, int ldout,
    const float* __restrict__ w, int cols)
{
    const int r = blockIdx.x;
    const float* x = in + (long long)r * ldin;
    float ss = 0.f;
    for (int c = threadIdx.x; c < cols; c += blockDim.x) {
        float v = x[c];
        ss += v * v;
    }
    __shared__ float sh[256];
    sh[threadIdx.x] = ss;
    __syncthreads();
    for (int s = 128; s > 0; s >>= 1) {
        if (threadIdx.x < s) sh[threadIdx.x] += sh[threadIdx.x + s];
        __syncthreads();
    }
    float scale = rsqrtf(sh[0] / (float)cols + EPSV);
    for (int c = threadIdx.x; c < cols; c += blockDim.x)
        out[(long long)r * ldout + c] = round_tf32(x[c] * scale * w[c]);
}

// ---------------------------------------------------------------------------
// RoPE (interleaved): rotates q rope dims (rounded), emits rounded k_rope.
// q nope dims are already tf32 (GEMM3 ROUND_OUT).
// ---------------------------------------------------------------------------
__global__ __launch_bounds__(512) void rope_kernel(
    float* __restrict__ q, const float* __restrict__ kvc,
    float* __restrict__ krope, const int* __restrict__ positions)
{
    const int s = blockIdx.x;
    const int t = threadIdx.x;
    const int h = t >> 5;
    const int i = t & 31;

    float pos = (float)positions[s];
    float inv = powf(10000.0f, -(2.0f * (float)i) / (float)ROPE);
    float ang = pos * inv;
    float sn, cs;
    sincosf(ang, &sn, &cs);

    float* qp = q + ((long long)s * NH + h) * QK + NOPE + 2 * i;
    float x1 = qp[0], x2 = qp[1];
    qp[0] = round_tf32(x1 * cs - x2 * sn);
    qp[1] = round_tf32(x2 * cs + x1 * sn);

    if (h == 0) {
        const float* kp = kvc + (long long)s * (KV_LORA + ROPE) + KV_LORA + 2 * i;
        float y1 = kp[0], y2 = kp[1];
        krope[(long long)s * ROPE + 2 * i]     = round_tf32(y1 * cs - y2 * sn);
        krope[(long long)s * ROPE + 2 * i + 1] = round_tf32(y2 * cs + y1 * sn);
    }
}

// ---------------------------------------------------------------------------
// Host launcher
// ---------------------------------------------------------------------------
static inline void* sym_addr(const void* symbol)
{
    void* p = nullptr;
    cudaGetSymbolAddress(&p, symbol);
    return p;
}

extern "C" void kernel_launch(void* const* d_in, const int* in_sizes, int n_in,
                              void* d_out, int out_size)
{
    const float* hidden  = (const float*)d_in[0];
    const float* w_qa    = (const float*)d_in[1];
    const float* qa_ln_w = (const float*)d_in[2];
    const float* w_qb    = (const float*)d_in[3];
    const float* w_kva   = (const float*)d_in[4];
    const float* kva_ln_w= (const float*)d_in[5];
    const float* w_kvb   = (const float*)d_in[6];
    const float* w_o     = (const float*)d_in[7];
    const int*   positions = (const int*)d_in[8];
    float* out = (float*)d_out;

    float* qc     = (float*)sym_addr(g_qc);
    float* q      = (float*)sym_addr(g_q);
    float* kvc    = (float*)sym_addr(g_kvc);
    float* kvlat  = (float*)sym_addr(g_kvlat);
    float* kv     = (float*)sym_addr(g_kv);
    float* krope  = (float*)sym_addr(g_krope);
    float* attn   = (float*)sym_addr(g_attn);

    float* hid_r  = (float*)sym_addr(g_hid_r);
    float* wqa_r  = (float*)sym_addr(g_wqa_r);
    float* wqb_r  = (float*)sym_addr(g_wqb_r);
    float* wkva_r = (float*)sym_addr(g_wkva_r);
    float* wkvb_r = (float*)sym_addr(g_wkvb_r);
    float* wo_r   = (float*)sym_addr(g_wo_r);

    const dim3 blk(256);

    const size_t smem_nn128 = (size_t)NSTAGE * (ASTG + BK * (128 + 8)) * 4; // 107,520
    const size_t smem_nn64  = (size_t)NSTAGE * (ASTG + BK * (64 + 8))  * 4; //  82,944

    cudaFuncSetAttribute(mma_gemm<128, false>,
                         cudaFuncAttributeMaxDynamicSharedMemorySize, (int)smem_nn128);
    cudaFuncSetAttribute(mma_gemm<128, true>,
                         cudaFuncAttributeMaxDynamicSharedMemorySize, (int)smem_nn128);
    cudaFuncSetAttribute(mma_gemm<64, false>,
                         cudaFuncAttributeMaxDynamicSharedMemorySize, (int)smem_nn64);
    cudaFuncSetAttribute(flash_attn_kernel,
                         cudaFuncAttributeMaxDynamicSharedMemorySize, FLASH_SMEM);

    // 0. tf32-round external inputs — single batched launch
    {
        CopyArgs a;
        const float* srcs[6] = { hidden, w_qa, w_qb, w_kva, w_kvb, w_o };
        float* dsts[6]       = { hid_r, wqa_r, wqb_r, wkva_r, wkvb_r, wo_r };
        long long ns[6] = {
            (long long)S * HIDDEN,
            (long long)HIDDEN * Q_LORA,
            (long long)Q_LORA * NH * QK,
            (long long)HIDDEN * (KV_LORA + ROPE),
            (long long)KV_LORA * NH * KVD,
            (long long)NH * V_DIM * HIDDEN };
        int pre = 0;
        for (int i = 0; i < 6; i++) {
            a.src[i] = (const float4*)srcs[i];
            a.dst[i] = (float4*)dsts[i];
            a.prefix[i] = pre;
            pre += (int)(ns[i] / 4 / 1024);   // all sizes divisible by 4096
        }
        a.prefix[6] = pre;
        round_copy_all_kernel<<<pre, blk>>>(a);
    }

    // 1. q_c_raw = hidden @ w_qa            [2048,1536] K=2048, BN=128
    mma_gemm<128, false><<<dim3(Q_LORA / 128, S / BM, 1), blk, smem_nn128>>>(
        hid_r, HIDDEN, wqa_r, Q_LORA, qc, Q_LORA,
        S, Q_LORA, HIDDEN, 1.0f);

    // 2. rmsnorm(q_c) in place (rounds output)
    rmsnorm_kernel<<<S, blk>>>(qc, Q_LORA, qc, Q_LORA, qa_ln_w, Q_LORA);

    // 3. q = q_c @ w_qb                     [2048,3072] K=1536, BN=128
    mma_gemm<128, true><<<dim3((NH * QK) / 128, S / BM, 1), blk, smem_nn128>>>(
        qc, Q_LORA, wqb_r, NH * QK, q, NH * QK,
        S, NH * QK, Q_LORA, 1.0f);

    // 4. kv_c = hidden @ w_kva              [2048,576] K=2048, BN=64
    mma_gemm<64, false><<<dim3((KV_LORA + ROPE) / 64, S / BM, 1), blk, smem_nn64>>>(
        hid_r, HIDDEN, wkva_r, KV_LORA + ROPE, kvc, KV_LORA + ROPE,
        S, KV_LORA + ROPE, HIDDEN, 1.0f);

    // 5. kv_lat = rmsnorm(kv_c[:, :512]) (rounds output)
    rmsnorm_kernel<<<S, blk>>>(kvc, KV_LORA + ROPE, kvlat, KV_LORA, kva_ln_w, KV_LORA);

    // 6. kv = kv_lat @ w_kvb                [2048,4096] K=512, BN=128
    mma_gemm<128, true><<<dim3((NH * KVD) / 128, S / BM, 1), blk, smem_nn128>>>(
        kvlat, KV_LORA, wkvb_r, NH * KVD, kv, NH * KVD,
        S, NH * KVD, KV_LORA, 1.0f);

    // 7. RoPE
    rope_kernel<<<S, 512>>>(q, kvc, krope, positions);

    // 8. fused causal flash attention -> attn (tf32-rounded)
    flash_attn_kernel<<<dim3(S / 128, NH), blk, FLASH_SMEM>>>(q, kv, krope, attn);

    // 9. out = attn @ w_o                   [2048,2048] K=2048, BN=128
    mma_gemm<128, false><<<dim3(HIDDEN / 128, S / BM, 1), blk, smem_nn128>>>(
        attn, NH * V_DIM, wo_r, HIDDEN, out, HIDDEN,
        S, HIDDEN, NH * V_DIM, 1.0f);
}

// round 13
// speedup vs baseline: 1.1047x; 1.0558x over previous
#include <cuda_runtime.h>
#include <cuda_bf16.h>
#include <math.h>

// ---------------------------------------------------------------------------
// Problem constants
// ---------------------------------------------------------------------------
#define S 2048
#define HIDDEN 2048
#define Q_LORA 1536
#define KV_LORA 512
#define NOPE 128
#define ROPE 64
#define V_DIM 128
#define NH 16
#define QK 192          // NOPE + ROPE
#define KVD 256         // NOPE + V_DIM
#define EPSV 1e-6f

// ---------------------------------------------------------------------------
// Scratch (static device globals)
// ---------------------------------------------------------------------------
__device__ float g_qc    [(size_t)S * Q_LORA];
__device__ float g_q     [(size_t)S * NH * QK];
__device__ float g_kvc   [(size_t)S * (KV_LORA + ROPE)];
__device__ float g_kvlat [(size_t)S * KV_LORA];
__device__ float g_kv    [(size_t)S * NH * KVD];
__device__ float g_krope [(size_t)S * ROPE];
__device__ float g_attn  [(size_t)S * NH * V_DIM];

// tf32-rounded copies of external inputs (weights + hidden)
__device__ float g_hid_r [(size_t)S * HIDDEN];
__device__ float g_wqa_r [(size_t)HIDDEN * Q_LORA];
__device__ float g_wqb_r [(size_t)Q_LORA * NH * QK];
__device__ float g_wkva_r[(size_t)HIDDEN * (KV_LORA + ROPE)];
__device__ float g_wkvb_r[(size_t)KV_LORA * NH * KVD];
__device__ float g_wo_r  [(size_t)NH * V_DIM * HIDDEN];

// ---------------------------------------------------------------------------
// tf32 helpers
// ---------------------------------------------------------------------------
__device__ __forceinline__ unsigned cvt_tf32(float x) {
    unsigned r;
    asm("cvt.rna.tf32.f32 %0, %1;" : "=r"(r) : "f"(x));
    return r;
}
__device__ __forceinline__ float round_tf32(float x) {
    return __uint_as_float(cvt_tf32(x));
}

__device__ __forceinline__ void cp_async16(float* dst, const float* src, bool pred) {
    unsigned d = (unsigned)__cvta_generic_to_shared(dst);
    int sz = pred ? 16 : 0;
    asm volatile("cp.async.cg.shared.global [%0], [%1], 16, %2;"
                 :: "r"(d), "l"(src), "r"(sz));
}

#define CP_COMMIT() asm volatile("cp.async.commit_group;")
#define CP_WAIT0()  asm volatile("cp.async.wait_group 0;")
#define CP_WAIT1()  asm volatile("cp.async.wait_group 1;")

#define MMA_TF32(d, a, b)                                                     \
    asm volatile(                                                             \
        "mma.sync.aligned.m16n8k8.row.col.f32.tf32.tf32.f32 "                 \
        "{%0,%1,%2,%3},{%4,%5,%6,%7},{%8,%9},{%0,%1,%2,%3};"                  \
        : "+f"((d)[0]), "+f"((d)[1]), "+f"((d)[2]), "+f"((d)[3])              \
        : "r"((a)[0]), "r"((a)[1]), "r"((a)[2]), "r"((a)[3]),                 \
          "r"((b)[0]), "r"((b)[1]))

// ---------------------------------------------------------------------------
// tf32 tensor-core GEMM: C[M,N] = alpha * A[M,K] @ B, row-major.
// Inputs MUST already be tf32-rounded (no cvt in the inner loop).
// ROUND_OUT: round outputs to tf32 (for tensors feeding later GEMMs)
// CTA tile 128 x BNv x 32, 256 threads = 8 warps (4m x 2n),
// warp tile 32 x (BNv/2). 3-stage cp.async pipeline, 2 CTAs/SM.
// R10 lesson: BNv=128 for large GEMMs (smaller BN loses more per-CTA
// efficiency than wave packing gains).
// ---------------------------------------------------------------------------
#define BM 128
#define BK 32
#define AST 36                   // smem stride for A tiles
#define ASTG (BM * AST)          // 4608 floats per A stage
#define NSTAGE 3

template <int BNv, bool ROUND_OUT>
__global__ __launch_bounds__(256, 2) void mma_gemm(
    const float* __restrict__ A, int lda,
    const float* __restrict__ B, int ldb,
    float* __restrict__ C, int ldc,
    int M, int N, int K, float alpha)
{
    constexpr int NT   = BNv / 16;                 // n-tiles per warp
    constexpr int BST  = BNv + 8;                  // k-major B smem stride
    constexpr int BSTG = BK * BST;

    const int bm = blockIdx.y * BM;
    const int bn = blockIdx.x * BNv;

    const int niter = K / BK;

    extern __shared__ float smem[];
    float* As = smem;                     // [NSTAGE][ASTG]
    float* Bs = smem + NSTAGE * ASTG;     // [NSTAGE][BSTG]

    const int tid  = threadIdx.x;
    const int lane = tid & 31;
    const int wid  = tid >> 5;
    const int wm   = wid & 3;             // warp row block (32 rows)
    const int wn   = wid >> 2;            // warp col block (BNv/2 cols)

    float acc[2][NT][4];
#pragma unroll
    for (int mt = 0; mt < 2; mt++)
#pragma unroll
        for (int nt = 0; nt < NT; nt++)
#pragma unroll
            for (int i = 0; i < 4; i++) acc[mt][nt][i] = 0.f;

    auto load_A = [&](int stage, int k0) {
#pragma unroll
        for (int p = 0; p < 4; p++) {
            int lin = p * 256 + tid;
            int r = lin >> 3, cq = lin & 7;
            cp_async16(As + stage * ASTG + r * AST + cq * 4,
                       A + (long long)(bm + r) * lda + k0 + cq * 4, true);
        }
    };
    auto load_B = [&](int stage, int k0) {
#pragma unroll
        for (int p = 0; p < BNv / 32; p++) {
            int lin = p * 256 + tid;
            int r = lin / (BNv / 4);
            int cq = lin % (BNv / 4);
            bool pred = (bn + cq * 4) < N;
            cp_async16(Bs + stage * BSTG + r * BST + cq * 4,
                       B + (long long)(k0 + r) * ldb + bn + cq * 4, pred);
        }
    };

    // ---- pipeline prologue: stages 0 and 1 in flight ----
    load_A(0, 0); load_B(0, 0); CP_COMMIT();
    if (niter > 1) { load_A(1, BK); load_B(1, BK); CP_COMMIT(); }

    // ---- main loop ----
    for (int it = 0; it < niter; it++) {
        if (it + 1 < niter) CP_WAIT1(); else CP_WAIT0();
        __syncthreads();

        if (it + 2 < niter) {
            int stg = (it + 2) % NSTAGE;
            load_A(stg, (it + 2) * BK);
            load_B(stg, (it + 2) * BK);
            CP_COMMIT();
        }

        const int cur = it % NSTAGE;
        const float* Asb = As + cur * ASTG;
        const float* Bsb = Bs + cur * BSTG;

#pragma unroll
        for (int ks = 0; ks < BK / 8; ks++) {
            const int kq = ks * 8 + (lane & 3);
            unsigned af[2][4];
#pragma unroll
            for (int mt = 0; mt < 2; mt++) {
                int m0 = wm * 32 + mt * 16 + (lane >> 2);
                af[mt][0] = __float_as_uint(Asb[m0 * AST + kq]);
                af[mt][1] = __float_as_uint(Asb[(m0 + 8) * AST + kq]);
                af[mt][2] = __float_as_uint(Asb[m0 * AST + kq + 4]);
                af[mt][3] = __float_as_uint(Asb[(m0 + 8) * AST + kq + 4]);
            }
            unsigned bf[NT][2];
#pragma unroll
            for (int nt = 0; nt < NT; nt++) {
                int n0 = wn * (BNv / 2) + nt * 8 + (lane >> 2);
                bf[nt][0] = __float_as_uint(Bsb[kq * BST + n0]);
                bf[nt][1] = __float_as_uint(Bsb[(kq + 4) * BST + n0]);
            }
#pragma unroll
            for (int mt = 0; mt < 2; mt++)
#pragma unroll
                for (int nt = 0; nt < NT; nt++)
                    MMA_TF32(acc[mt][nt], af[mt], bf[nt]);
        }
    }

    // ---- epilogue ----
#pragma unroll
    for (int mt = 0; mt < 2; mt++) {
        int r0 = bm + wm * 32 + mt * 16 + (lane >> 2);
#pragma unroll
        for (int nt = 0; nt < NT; nt++) {
            int c0 = bn + wn * (BNv / 2) + nt * 8 + (lane & 3) * 2;
            if (c0 < N) {
                float x0 = acc[mt][nt][0] * alpha, x1 = acc[mt][nt][1] * alpha;
                float x2 = acc[mt][nt][2] * alpha, x3 = acc[mt][nt][3] * alpha;
                if (ROUND_OUT) {
                    x0 = round_tf32(x0); x1 = round_tf32(x1);
                    x2 = round_tf32(x2); x3 = round_tf32(x3);
                }
                *reinterpret_cast<float2*>(C + (long long)r0 * ldc + c0) =
                    make_float2(x0, x1);
                *reinterpret_cast<float2*>(C + (long long)(r0 + 8) * ldc + c0) =
                    make_float2(x2, x3);
            }
        }
    }
}

// ---------------------------------------------------------------------------
// Fused causal flash attention (tf32 mma, online softmax).
// Grid (16 q-tiles, 16 heads), 256 threads = 8 warps, each warp owns 16 rows.
// R11 lesson: NO Q-register caching — it pushed regs to the 255 ceiling and
// spilled; Q fragments are read from smem each k-tile (measured-fast R9 form).
// smem: Q 128x192(s196) | K 64x192(s196) | V 64x128(s136) | P 128x64(s68)
// ---------------------------------------------------------------------------
#define QST 196
#define KST 196
#define VST 136
#define PST 68
#define FL_Q 0
#define FL_K 25088
#define FL_V 37632
#define FL_P 46336
#define FLASH_SMEM ((46336 + 128 * PST) * 4)   // 220,160 bytes
#define NEGINF (-3.0e38f)

__global__ __launch_bounds__(256) void flash_attn_kernel(
    const float* __restrict__ q,
    const float* __restrict__ kv,
    const float* __restrict__ krope,
    float* __restrict__ attn)
{
    const int qt  = (int)gridDim.x - 1 - (int)blockIdx.x;  // heavy tiles first
    const int h   = blockIdx.y;
    const int bm  = qt * 128;
    const int nkt = bm / 64 + 2;
    const float scale = 0.07216878364870322f;  // 1/sqrt(192)

    extern __shared__ float sm[];
    float* Qs = sm + FL_Q;
    float* Ks = sm + FL_K;
    float* Vs = sm + FL_V;
    float* Ps = sm + FL_P;

    const int tid  = threadIdx.x;
    const int lane = tid & 31;
    const int wid  = tid >> 5;
    const int qr   = lane >> 2;
    const int qc   = lane & 3;
    const int row0 = wid * 16 + qr;        // this thread's base row in tile

    auto load_K = [&](int kt) {
        int t0 = kt * 64;
#pragma unroll
        for (int p = 0; p < 12; p++) {
            int lin = p * 256 + tid;
            int r = lin / 48, seg = lin % 48;
            const float* src = (seg < 32)
                ? kv + ((long long)(t0 + r) * NH + h) * KVD + seg * 4
                : krope + (long long)(t0 + r) * ROPE + (seg - 32) * 4;
            cp_async16(Ks + r * KST + seg * 4, src, true);
        }
    };
    auto load_V = [&](int kt) {
        int t0 = kt * 64;
#pragma unroll
        for (int p = 0; p < 8; p++) {
            int lin = p * 256 + tid;
            int r = lin / 32, c = lin % 32;
            cp_async16(Vs + r * VST + c * 4,
                       kv + ((long long)(t0 + r) * NH + h) * KVD + NOPE + c * 4,
                       true);
        }
    };

    // ---- prologue: Q tile + first K/V tile ----
#pragma unroll
    for (int p = 0; p < 24; p++) {
        int lin = p * 256 + tid;
        int r = lin / 48, seg = lin % 48;
        cp_async16(Qs + r * QST + seg * 4,
                   q + ((long long)(bm + r) * NH + h) * QK + seg * 4, true);
    }
    load_K(0);
    load_V(0);
    CP_COMMIT();
    CP_WAIT0();
    __syncthreads();

    float o[16][4];
#pragma unroll
    for (int nt = 0; nt < 16; nt++)
#pragma unroll
        for (int i = 0; i < 4; i++) o[nt][i] = 0.f;
    float mA = NEGINF, mB = NEGINF, lA = 0.f, lB = 0.f;

    for (int kt = 0; kt < nkt; kt++) {
        const int t0 = kt * 64;

        // ---- S = Q K^T (16x64 per warp, K=192) ----
        float sacc[8][4];
#pragma unroll
        for (int nt = 0; nt < 8; nt++)
#pragma unroll
            for (int i = 0; i < 4; i++) sacc[nt][i] = 0.f;

#pragma unroll
        for (int ks = 0; ks < 24; ks++) {
            const int kq = ks * 8 + qc;
            unsigned af[4];
            af[0] = __float_as_uint(Qs[row0 * QST + kq]);
            af[1] = __float_as_uint(Qs[(row0 + 8) * QST + kq]);
            af[2] = __float_as_uint(Qs[row0 * QST + kq + 4]);
            af[3] = __float_as_uint(Qs[(row0 + 8) * QST + kq + 4]);
            unsigned bf[8][2];
#pragma unroll
            for (int nt = 0; nt < 8; nt++) {
                int n0 = nt * 8 + qr;
                bf[nt][0] = __float_as_uint(Ks[n0 * KST + kq]);
                bf[nt][1] = __float_as_uint(Ks[n0 * KST + kq + 4]);
            }
#pragma unroll
            for (int nt = 0; nt < 8; nt++)
                MMA_TF32(sacc[nt], af, bf[nt]);
        }

        // ---- scale + causal mask + tile row-max ----
        const int rowA = bm + row0;
        const int rowB = rowA + 8;
        float tmA = NEGINF, tmB = NEGINF;
#pragma unroll
        for (int nt = 0; nt < 8; nt++) {
            int c0 = t0 + nt * 8 + qc * 2;
            float v0 = (c0     <= rowA) ? sacc[nt][0] * scale : NEGINF;
            float v1 = (c0 + 1 <= rowA) ? sacc[nt][1] * scale : NEGINF;
            float v2 = (c0     <= rowB) ? sacc[nt][2] * scale : NEGINF;
            float v3 = (c0 + 1 <= rowB) ? sacc[nt][3] * scale : NEGINF;
            sacc[nt][0] = v0; sacc[nt][1] = v1;
            sacc[nt][2] = v2; sacc[nt][3] = v3;
            tmA = fmaxf(tmA, fmaxf(v0, v1));
            tmB = fmaxf(tmB, fmaxf(v2, v3));
        }
        tmA = fmaxf(tmA, __shfl_xor_sync(0xffffffffu, tmA, 1));
        tmA = fmaxf(tmA, __shfl_xor_sync(0xffffffffu, tmA, 2));
        tmB = fmaxf(tmB, __shfl_xor_sync(0xffffffffu, tmB, 1));
        tmB = fmaxf(tmB, __shfl_xor_sync(0xffffffffu, tmB, 2));

        const float mA2 = fmaxf(mA, tmA);
        const float mB2 = fmaxf(mB, tmB);
        const float aA = __expf(mA - mA2);
        const float aB = __expf(mB - mB2);

        // ---- P = exp(S - m), rounded tf32; accumulate row sums ----
        float sA = 0.f, sB = 0.f;
#pragma unroll
        for (int nt = 0; nt < 8; nt++) {
            float p0 = round_tf32(__expf(sacc[nt][0] - mA2));
            float p1 = round_tf32(__expf(sacc[nt][1] - mA2));
            float p2 = round_tf32(__expf(sacc[nt][2] - mB2));
            float p3 = round_tf32(__expf(sacc[nt][3] - mB2));
            sA += p0 + p1;
            sB += p2 + p3;
            int c = nt * 8 + qc * 2;
            *reinterpret_cast<float2*>(Ps + row0 * PST + c) = make_float2(p0, p1);
            *reinterpret_cast<float2*>(Ps + (row0 + 8) * PST + c) = make_float2(p2, p3);
        }
        sA += __shfl_xor_sync(0xffffffffu, sA, 1);
        sA += __shfl_xor_sync(0xffffffffu, sA, 2);
        sB += __shfl_xor_sync(0xffffffffu, sB, 1);
        sB += __shfl_xor_sync(0xffffffffu, sB, 2);

        lA = lA * aA + sA;
        lB = lB * aB + sB;
        mA = mA2;
        mB = mB2;
#pragma unroll
        for (int nt = 0; nt < 16; nt++) {
            o[nt][0] *= aA; o[nt][1] *= aA;
            o[nt][2] *= aB; o[nt][3] *= aB;
        }

        __syncthreads();   // all warps done with Ks, Ps written

        // prefetch next K while PV runs (K buffer is free now)
        if (kt + 1 < nkt) { load_K(kt + 1); CP_COMMIT(); }

        // ---- O += P @ V (16x128 per warp, K=64) ----
#pragma unroll
        for (int ks = 0; ks < 8; ks++) {
            const int kq = ks * 8 + qc;
            unsigned af[4];
            af[0] = __float_as_uint(Ps[row0 * PST + kq]);
            af[1] = __float_as_uint(Ps[(row0 + 8) * PST + kq]);
            af[2] = __float_as_uint(Ps[row0 * PST + kq + 4]);
            af[3] = __float_as_uint(Ps[(row0 + 8) * PST + kq + 4]);
#pragma unroll
            for (int nt = 0; nt < 16; nt++) {
                unsigned bf[2];
                int n0 = nt * 8 + qr;
                bf[0] = __float_as_uint(Vs[kq * VST + n0]);
                bf[1] = __float_as_uint(Vs[(kq + 4) * VST + n0]);
                MMA_TF32(o[nt], af, bf);
            }
        }

        __syncthreads();   // all warps done with Vs, Ps

        if (kt + 1 < nkt) {
            load_V(kt + 1);
            CP_COMMIT();
            CP_WAIT0();
            __syncthreads();   // next K/V visible to all
        }
    }

    // ---- epilogue: O / l, rounded tf32 ----
    const float invA = 1.f / lA;
    const float invB = 1.f / lB;
    const long long baseA = ((long long)(bm + row0) * NH + h) * V_DIM;
    const long long baseB = ((long long)(bm + row0 + 8) * NH + h) * V_DIM;
#pragma unroll
    for (int nt = 0; nt < 16; nt++) {
        int c = nt * 8 + qc * 2;
        *reinterpret_cast<float2*>(attn + baseA + c) =
            make_float2(round_tf32(o[nt][0] * invA), round_tf32(o[nt][1] * invA));
        *reinterpret_cast<float2*>(attn + baseB + c) =
            make_float2(round_tf32(o[nt][2] * invB), round_tf32(o[nt][3] * invB));
    }
}

// ---------------------------------------------------------------------------
// Batched tf32 pre-rounding copy: all 6 tensors in ONE launch.
// Each block handles exactly one 1024-float4 (16 KB) chunk; every segment's
// n4 is a multiple of 1024.
// ---------------------------------------------------------------------------
struct CopyArgs {
    const float4* src[6];
    float4*       dst[6];
    int           prefix[7];   // chunk-index prefix sums
};

__global__ __launch_bounds__(256) void round_copy_all_kernel(CopyArgs a)
{
    const int b = blockIdx.x;
    int s = 0;
#pragma unroll
    for (int i = 1; i < 6; i++)
        if (b >= a.prefix[i]) s = i;
    const int chunk = b - a.prefix[s];
    const float4* in  = a.src[s] + (long long)chunk * 1024;
    float4*       out = a.dst[s] + (long long)chunk * 1024;

    const int i0 = threadIdx.x;
    float4 x = in[i0];
    float4 y = in[i0 + 256];
    float4 z = in[i0 + 512];
    float4 w = in[i0 + 768];
    x.x = round_tf32(x.x); x.y = round_tf32(x.y);
    x.z = round_tf32(x.z); x.w = round_tf32(x.w);
    y.x = round_tf32(y.x); y.y = round_tf32(y.y);
    y.z = round_tf32(y.z); y.w = round_tf32(y.w);
    z.x = round_tf32(z.x); z.y = round_tf32(z.y);
    z.z = round_tf32(z.z); z.w = round_tf32(z.w);
    w.x = round_tf32(w.x); w.y = round_tf32(w.y);
    w.z = round_tf32(w.z); w.w = round_tf32(w.w);
    out[i0]       = x;
    out[i0 + 256] = y;
    out[i0 + 512] = z;
    out[i0 + 768] = w;
}

// ---------------------------------------------------------------------------
// RMSNorm: one block per row; output rounded to tf32
// ---------------------------------------------------------------------------
__global__ __launch_bounds__(256) void rmsnorm_kernel(
    const float* __restrict__ in, int ldin,
    float* __restrict__ out, int ldout,
    const float* __restrict__ w, int cols)
{
    const int r = blockIdx.x;
    const float* x = in + (long long)r * ldin;
    float ss = 0.f;
    for (int c = threadIdx.x; c < cols; c += blockDim.x) {
        float v = x[c];
        ss += v * v;
    }
    __shared__ float sh[256];
    sh[threadIdx.x] = ss;
    __syncthreads();
    for (int s = 128; s > 0; s >>= 1) {
        if (threadIdx.x < s) sh[threadIdx.x] += sh[threadIdx.x + s];
        __syncthreads();
    }
    float scale = rsqrtf(sh[0] / (float)cols + EPSV);
    for (int c = threadIdx.x; c < cols; c += blockDim.x)
        out[(long long)r * ldout + c] = round_tf32(x[c] * scale * w[c]);
}

// ---------------------------------------------------------------------------
// RoPE (interleaved): rotates q rope dims (rounded), emits rounded k_rope.
// q nope dims are already tf32 (GEMM3 ROUND_OUT).
// ---------------------------------------------------------------------------
__global__ __launch_bounds__(512) void rope_kernel(
    float* __restrict__ q, const float* __restrict__ kvc,
    float* __restrict__ krope, const int* __restrict__ positions)
{
    const int s = blockIdx.x;
    const int t = threadIdx.x;
    const int h = t >> 5;
    const int i = t & 31;

    float pos = (float)positions[s];
    float inv = powf(10000.0f, -(2.0f * (float)i) / (float)ROPE);
    float ang = pos * inv;
    float sn, cs;
    sincosf(ang, &sn, &cs);

    float* qp = q + ((long long)s * NH + h) * QK + NOPE + 2 * i;
    float x1 = qp[0], x2 = qp[1];
    qp[0] = round_tf32(x1 * cs - x2 * sn);
    qp[1] = round_tf32(x2 * cs + x1 * sn);

    if (h == 0) {
        const float* kp = kvc + (long long)s * (KV_LORA + ROPE) + KV_LORA + 2 * i;
        float y1 = kp[0], y2 = kp[1];
        krope[(long long)s * ROPE + 2 * i]     = round_tf32(y1 * cs - y2 * sn);
        krope[(long long)s * ROPE + 2 * i + 1] = round_tf32(y2 * cs + y1 * sn);
    }
}

// ---------------------------------------------------------------------------
// Host launcher
// ---------------------------------------------------------------------------
static inline void* sym_addr(const void* symbol)
{
    void* p = nullptr;
    cudaGetSymbolAddress(&p, symbol);
    return p;
}

extern "C" void kernel_launch(void* const* d_in, const int* in_sizes, int n_in,
                              void* d_out, int out_size)
{
    const float* hidden  = (const float*)d_in[0];
    const float* w_qa    = (const float*)d_in[1];
    const float* qa_ln_w = (const float*)d_in[2];
    const float* w_qb    = (const float*)d_in[3];
    const float* w_kva   = (const float*)d_in[4];
    const float* kva_ln_w= (const float*)d_in[5];
    const float* w_kvb   = (const float*)d_in[6];
    const float* w_o     = (const float*)d_in[7];
    const int*   positions = (const int*)d_in[8];
    float* out = (float*)d_out;

    float* qc     = (float*)sym_addr(g_qc);
    float* q      = (float*)sym_addr(g_q);
    float* kvc    = (float*)sym_addr(g_kvc);
    float* kvlat  = (float*)sym_addr(g_kvlat);
    float* kv     = (float*)sym_addr(g_kv);
    float* krope  = (float*)sym_addr(g_krope);
    float* attn   = (float*)sym_addr(g_attn);

    float* hid_r  = (float*)sym_addr(g_hid_r);
    float* wqa_r  = (float*)sym_addr(g_wqa_r);
    float* wqb_r  = (float*)sym_addr(g_wqb_r);
    float* wkva_r = (float*)sym_addr(g_wkva_r);
    float* wkvb_r = (float*)sym_addr(g_wkvb_r);
    float* wo_r   = (float*)sym_addr(g_wo_r);

    const dim3 blk(256);

    const size_t smem_nn128 = (size_t)NSTAGE * (ASTG + BK * (128 + 8)) * 4; // 107,520
    const size_t smem_nn64  = (size_t)NSTAGE * (ASTG + BK * (64 + 8))  * 4; //  82,944

    cudaFuncSetAttribute(mma_gemm<128, false>,
                         cudaFuncAttributeMaxDynamicSharedMemorySize, (int)smem_nn128);
    cudaFuncSetAttribute(mma_gemm<128, true>,
                         cudaFuncAttributeMaxDynamicSharedMemorySize, (int)smem_nn128);
    cudaFuncSetAttribute(mma_gemm<64, false>,
                         cudaFuncAttributeMaxDynamicSharedMemorySize, (int)smem_nn64);
    cudaFuncSetAttribute(flash_attn_kernel,
                         cudaFuncAttributeMaxDynamicSharedMemorySize, FLASH_SMEM);

    // 0. tf32-round external inputs — single batched launch
    {
        CopyArgs a;
        const float* srcs[6] = { hidden, w_qa, w_qb, w_kva, w_kvb, w_o };
        float* dsts[6]       = { hid_r, wqa_r, wqb_r, wkva_r, wkvb_r, wo_r };
        long long ns[6] = {
            (long long)S * HIDDEN,
            (long long)HIDDEN * Q_LORA,
            (long long)Q_LORA * NH * QK,
            (long long)HIDDEN * (KV_LORA + ROPE),
            (long long)KV_LORA * NH * KVD,
            (long long)NH * V_DIM * HIDDEN };
        int pre = 0;
        for (int i = 0; i < 6; i++) {
            a.src[i] = (const float4*)srcs[i];
            a.dst[i] = (float4*)dsts[i];
            a.prefix[i] = pre;
            pre += (int)(ns[i] / 4 / 1024);   // all sizes divisible by 4096
        }
        a.prefix[6] = pre;
        round_copy_all_kernel<<<pre, blk>>>(a);
    }

    // 1. q_c_raw = hidden @ w_qa            [2048,1536] K=2048, BN=128
    mma_gemm<128, false><<<dim3(Q_LORA / 128, S / BM, 1), blk, smem_nn128>>>(
        hid_r, HIDDEN, wqa_r, Q_LORA, qc, Q_LORA,
        S, Q_LORA, HIDDEN, 1.0f);

    // 2. rmsnorm(q_c) in place (rounds output)
    rmsnorm_kernel<<<S, blk>>>(qc, Q_LORA, qc, Q_LORA, qa_ln_w, Q_LORA);

    // 3. q = q_c @ w_qb                     [2048,3072] K=1536, BN=128
    mma_gemm<128, true><<<dim3((NH * QK) / 128, S / BM, 1), blk, smem_nn128>>>(
        qc, Q_LORA, wqb_r, NH * QK, q, NH * QK,
        S, NH * QK, Q_LORA, 1.0f);

    // 4. kv_c = hidden @ w_kva              [2048,576] K=2048, BN=64
    mma_gemm<64, false><<<dim3((KV_LORA + ROPE) / 64, S / BM, 1), blk, smem_nn64>>>(
        hid_r, HIDDEN, wkva_r, KV_LORA + ROPE, kvc, KV_LORA + ROPE,
        S, KV_LORA + ROPE, HIDDEN, 1.0f);

    // 5. kv_lat = rmsnorm(kv_c[:, :512]) (rounds output)
    rmsnorm_kernel<<<S, blk>>>(kvc, KV_LORA + ROPE, kvlat, KV_LORA, kva_ln_w, KV_LORA);

    // 6. kv = kv_lat @ w_kvb                [2048,4096] K=512, BN=128
    mma_gemm<128, true><<<dim3((NH * KVD) / 128, S / BM, 1), blk, smem_nn128>>>(
        kvlat, KV_LORA, wkvb_r, NH * KVD, kv, NH * KVD,
        S, NH * KVD, KV_LORA, 1.0f);

    // 7. RoPE
    rope_kernel<<<S, 512>>>(q, kvc, krope, positions);

    // 8. fused causal flash attention -> attn (tf32-rounded)
    flash_attn_kernel<<<dim3(S / 128, NH), blk, FLASH_SMEM>>>(q, kv, krope, attn);

    // 9. out = attn @ w_o                   [2048,2048] K=2048, BN=128
    mma_gemm<128, false><<<dim3(HIDDEN / 128, S / BM, 1), blk, smem_nn128>>>(
        attn, NH * V_DIM, wo_r, HIDDEN, out, HIDDEN,
        S, HIDDEN, NH * V_DIM, 1.0f);
}

// round 14
// speedup vs baseline: 1.1700x; 1.0591x over previous
#include <cuda_runtime.h>
#include <cuda_bf16.h>
#include <math.h>

// ---------------------------------------------------------------------------
// Problem constants
// ---------------------------------------------------------------------------
#define S 2048
#define HIDDEN 2048
#define Q_LORA 1536
#define KV_LORA 512
#define NOPE 128
#define ROPE 64
#define V_DIM 128
#define NH 16
#define QK 192          // NOPE + ROPE
#define KVD 256         // NOPE + V_DIM
#define EPSV 1e-6f
#define NCAT 2112       // Q_LORA + KV_LORA + ROPE (fused GEMM1+kv_c width)

// ---------------------------------------------------------------------------
// Scratch (static device globals)
// ---------------------------------------------------------------------------
__device__ float g_qc    [(size_t)S * Q_LORA];        // rmsnorm'd q_c
__device__ float g_qcat  [(size_t)S * NCAT];          // fused GEMM1+kv_c output
__device__ float g_kvlat [(size_t)S * KV_LORA];
__device__ float g_kv    [(size_t)S * NH * KVD];
__device__ float g_krope [(size_t)S * ROPE];
__device__ float g_q     [(size_t)S * NH * QK];
__device__ float g_attn  [(size_t)S * NH * V_DIM];

// tf32-rounded copies of external inputs
__device__ float g_hid_r [(size_t)S * HIDDEN];
__device__ float g_wcat_r[(size_t)HIDDEN * NCAT];     // [w_qa | w_kva] col-concat
__device__ float g_wqb_r [(size_t)Q_LORA * NH * QK];
__device__ float g_wkvb_r[(size_t)KV_LORA * NH * KVD];
__device__ float g_wo_r  [(size_t)NH * V_DIM * HIDDEN];

// ---------------------------------------------------------------------------
// tf32 helpers
// ---------------------------------------------------------------------------
__device__ __forceinline__ unsigned cvt_tf32(float x) {
    unsigned r;
    asm("cvt.rna.tf32.f32 %0, %1;" : "=r"(r) : "f"(x));
    return r;
}
__device__ __forceinline__ float round_tf32(float x) {
    return __uint_as_float(cvt_tf32(x));
}

__device__ __forceinline__ void cp_async16(float* dst, const float* src, bool pred) {
    unsigned d = (unsigned)__cvta_generic_to_shared(dst);
    int sz = pred ? 16 : 0;
    asm volatile("cp.async.cg.shared.global [%0], [%1], 16, %2;"
                 :: "r"(d), "l"(src), "r"(sz));
}

#define CP_COMMIT() asm volatile("cp.async.commit_group;")
#define CP_WAIT0()  asm volatile("cp.async.wait_group 0;")
#define CP_WAIT1()  asm volatile("cp.async.wait_group 1;")

#define MMA_TF32(d, a, b)                                                     \
    asm volatile(                                                             \
        "mma.sync.aligned.m16n8k8.row.col.f32.tf32.tf32.f32 "                 \
        "{%0,%1,%2,%3},{%4,%5,%6,%7},{%8,%9},{%0,%1,%2,%3};"                  \
        : "+f"((d)[0]), "+f"((d)[1]), "+f"((d)[2]), "+f"((d)[3])              \
        : "r"((a)[0]), "r"((a)[1]), "r"((a)[2]), "r"((a)[3]),                 \
          "r"((b)[0]), "r"((b)[1]))

// ---------------------------------------------------------------------------
// tf32 tensor-core GEMM: C[M,N] = alpha * A[M,K] @ B, row-major.
// Inputs MUST already be tf32-rounded (no cvt in the inner loop).
// ROUND_OUT: round outputs to tf32.
// CTA tile 128 x 128 x 32, 256 threads = 8 warps (4m x 2n),
// warp tile 32 x 64. 3-stage cp.async pipeline, 2 CTAs/SM.
// R10 lesson: keep BN=128 for all large GEMMs.
// ---------------------------------------------------------------------------
#define BM 128
#define BK 32
#define BNv 128
#define AST 36                   // smem stride for A tiles
#define ASTG (BM * AST)          // 4608 floats per A stage
#define NSTAGE 3
#define BST (BNv + 8)            // k-major B smem stride
#define BSTG (BK * BST)
#define GEMM_SMEM ((size_t)NSTAGE * (ASTG + BSTG) * 4)   // 107,520 B

template <bool ROUND_OUT>
__global__ __launch_bounds__(256, 2) void mma_gemm(
    const float* __restrict__ A, int lda,
    const float* __restrict__ B, int ldb,
    float* __restrict__ C, int ldc,
    int M, int N, int K, float alpha)
{
    constexpr int NT = BNv / 16;                   // 8 n-tiles per warp

    const int bm = blockIdx.y * BM;
    const int bn = blockIdx.x * BNv;

    const int niter = K / BK;

    extern __shared__ float smem[];
    float* As = smem;                     // [NSTAGE][ASTG]
    float* Bs = smem + NSTAGE * ASTG;     // [NSTAGE][BSTG]

    const int tid  = threadIdx.x;
    const int lane = tid & 31;
    const int wid  = tid >> 5;
    const int wm   = wid & 3;             // warp row block (32 rows)
    const int wn   = wid >> 2;            // warp col block (64 cols)

    float acc[2][NT][4];
#pragma unroll
    for (int mt = 0; mt < 2; mt++)
#pragma unroll
        for (int nt = 0; nt < NT; nt++)
#pragma unroll
            for (int i = 0; i < 4; i++) acc[mt][nt][i] = 0.f;

    auto load_A = [&](int stage, int k0) {
#pragma unroll
        for (int p = 0; p < 4; p++) {
            int lin = p * 256 + tid;
            int r = lin >> 3, cq = lin & 7;
            cp_async16(As + stage * ASTG + r * AST + cq * 4,
                       A + (long long)(bm + r) * lda + k0 + cq * 4, true);
        }
    };
    auto load_B = [&](int stage, int k0) {
#pragma unroll
        for (int p = 0; p < BNv / 32; p++) {
            int lin = p * 256 + tid;
            int r = lin / (BNv / 4);
            int cq = lin % (BNv / 4);
            bool pred = (bn + cq * 4) < N;
            cp_async16(Bs + stage * BSTG + r * BST + cq * 4,
                       B + (long long)(k0 + r) * ldb + bn + cq * 4, pred);
        }
    };

    // ---- pipeline prologue ----
    load_A(0, 0); load_B(0, 0); CP_COMMIT();
    if (niter > 1) { load_A(1, BK); load_B(1, BK); CP_COMMIT(); }

    // ---- main loop ----
    for (int it = 0; it < niter; it++) {
        if (it + 1 < niter) CP_WAIT1(); else CP_WAIT0();
        __syncthreads();

        if (it + 2 < niter) {
            int stg = (it + 2) % NSTAGE;
            load_A(stg, (it + 2) * BK);
            load_B(stg, (it + 2) * BK);
            CP_COMMIT();
        }

        const int cur = it % NSTAGE;
        const float* Asb = As + cur * ASTG;
        const float* Bsb = Bs + cur * BSTG;

#pragma unroll
        for (int ks = 0; ks < BK / 8; ks++) {
            const int kq = ks * 8 + (lane & 3);
            unsigned af[2][4];
#pragma unroll
            for (int mt = 0; mt < 2; mt++) {
                int m0 = wm * 32 + mt * 16 + (lane >> 2);
                af[mt][0] = __float_as_uint(Asb[m0 * AST + kq]);
                af[mt][1] = __float_as_uint(Asb[(m0 + 8) * AST + kq]);
                af[mt][2] = __float_as_uint(Asb[m0 * AST + kq + 4]);
                af[mt][3] = __float_as_uint(Asb[(m0 + 8) * AST + kq + 4]);
            }
            unsigned bf[NT][2];
#pragma unroll
            for (int nt = 0; nt < NT; nt++) {
                int n0 = wn * 64 + nt * 8 + (lane >> 2);
                bf[nt][0] = __float_as_uint(Bsb[kq * BST + n0]);
                bf[nt][1] = __float_as_uint(Bsb[(kq + 4) * BST + n0]);
            }
#pragma unroll
            for (int mt = 0; mt < 2; mt++)
#pragma unroll
                for (int nt = 0; nt < NT; nt++)
                    MMA_TF32(acc[mt][nt], af[mt], bf[nt]);
        }
    }

    // ---- epilogue ----
#pragma unroll
    for (int mt = 0; mt < 2; mt++) {
        int r0 = bm + wm * 32 + mt * 16 + (lane >> 2);
#pragma unroll
        for (int nt = 0; nt < NT; nt++) {
            int c0 = bn + wn * 64 + nt * 8 + (lane & 3) * 2;
            if (c0 < N) {
                float x0 = acc[mt][nt][0] * alpha, x1 = acc[mt][nt][1] * alpha;
                float x2 = acc[mt][nt][2] * alpha, x3 = acc[mt][nt][3] * alpha;
                if (ROUND_OUT) {
                    x0 = round_tf32(x0); x1 = round_tf32(x1);
                    x2 = round_tf32(x2); x3 = round_tf32(x3);
                }
                *reinterpret_cast<float2*>(C + (long long)r0 * ldc + c0) =
                    make_float2(x0, x1);
                *reinterpret_cast<float2*>(C + (long long)(r0 + 8) * ldc + c0) =
                    make_float2(x2, x3);
            }
        }
    }
}

// ---------------------------------------------------------------------------
// Fused causal flash attention (tf32 mma, online softmax). R9 form (no
// Q-register caching; R11 showed it spills at the 255-reg ceiling).
// smem: Q 128x192(s196) | K 64x192(s196) | V 64x128(s136) | P 128x64(s68)
// ---------------------------------------------------------------------------
#define QST 196
#define KST 196
#define VST 136
#define PST 68
#define FL_Q 0
#define FL_K 25088
#define FL_V 37632
#define FL_P 46336
#define FLASH_SMEM ((46336 + 128 * PST) * 4)   // 220,160 bytes
#define NEGINF (-3.0e38f)

__global__ __launch_bounds__(256) void flash_attn_kernel(
    const float* __restrict__ q,
    const float* __restrict__ kv,
    const float* __restrict__ krope,
    float* __restrict__ attn)
{
    const int qt  = (int)gridDim.x - 1 - (int)blockIdx.x;  // heavy tiles first
    const int h   = blockIdx.y;
    const int bm  = qt * 128;
    const int nkt = bm / 64 + 2;
    const float scale = 0.07216878364870322f;  // 1/sqrt(192)

    extern __shared__ float sm[];
    float* Qs = sm + FL_Q;
    float* Ks = sm + FL_K;
    float* Vs = sm + FL_V;
    float* Ps = sm + FL_P;

    const int tid  = threadIdx.x;
    const int lane = tid & 31;
    const int wid  = tid >> 5;
    const int qr   = lane >> 2;
    const int qc   = lane & 3;
    const int row0 = wid * 16 + qr;

    auto load_K = [&](int kt) {
        int t0 = kt * 64;
#pragma unroll
        for (int p = 0; p < 12; p++) {
            int lin = p * 256 + tid;
            int r = lin / 48, seg = lin % 48;
            const float* src = (seg < 32)
                ? kv + ((long long)(t0 + r) * NH + h) * KVD + seg * 4
                : krope + (long long)(t0 + r) * ROPE + (seg - 32) * 4;
            cp_async16(Ks + r * KST + seg * 4, src, true);
        }
    };
    auto load_V = [&](int kt) {
        int t0 = kt * 64;
#pragma unroll
        for (int p = 0; p < 8; p++) {
            int lin = p * 256 + tid;
            int r = lin / 32, c = lin % 32;
            cp_async16(Vs + r * VST + c * 4,
                       kv + ((long long)(t0 + r) * NH + h) * KVD + NOPE + c * 4,
                       true);
        }
    };

    // ---- prologue: Q tile + first K/V tile ----
#pragma unroll
    for (int p = 0; p < 24; p++) {
        int lin = p * 256 + tid;
        int r = lin / 48, seg = lin % 48;
        cp_async16(Qs + r * QST + seg * 4,
                   q + ((long long)(bm + r) * NH + h) * QK + seg * 4, true);
    }
    load_K(0);
    load_V(0);
    CP_COMMIT();
    CP_WAIT0();
    __syncthreads();

    float o[16][4];
#pragma unroll
    for (int nt = 0; nt < 16; nt++)
#pragma unroll
        for (int i = 0; i < 4; i++) o[nt][i] = 0.f;
    float mA = NEGINF, mB = NEGINF, lA = 0.f, lB = 0.f;

    for (int kt = 0; kt < nkt; kt++) {
        const int t0 = kt * 64;

        // ---- S = Q K^T ----
        float sacc[8][4];
#pragma unroll
        for (int nt = 0; nt < 8; nt++)
#pragma unroll
            for (int i = 0; i < 4; i++) sacc[nt][i] = 0.f;

#pragma unroll
        for (int ks = 0; ks < 24; ks++) {
            const int kq = ks * 8 + qc;
            unsigned af[4];
            af[0] = __float_as_uint(Qs[row0 * QST + kq]);
            af[1] = __float_as_uint(Qs[(row0 + 8) * QST + kq]);
            af[2] = __float_as_uint(Qs[row0 * QST + kq + 4]);
            af[3] = __float_as_uint(Qs[(row0 + 8) * QST + kq + 4]);
            unsigned bf[8][2];
#pragma unroll
            for (int nt = 0; nt < 8; nt++) {
                int n0 = nt * 8 + qr;
                bf[nt][0] = __float_as_uint(Ks[n0 * KST + kq]);
                bf[nt][1] = __float_as_uint(Ks[n0 * KST + kq + 4]);
            }
#pragma unroll
            for (int nt = 0; nt < 8; nt++)
                MMA_TF32(sacc[nt], af, bf[nt]);
        }

        // ---- scale + causal mask + tile row-max ----
        const int rowA = bm + row0;
        const int rowB = rowA + 8;
        float tmA = NEGINF, tmB = NEGINF;
#pragma unroll
        for (int nt = 0; nt < 8; nt++) {
            int c0 = t0 + nt * 8 + qc * 2;
            float v0 = (c0     <= rowA) ? sacc[nt][0] * scale : NEGINF;
            float v1 = (c0 + 1 <= rowA) ? sacc[nt][1] * scale : NEGINF;
            float v2 = (c0     <= rowB) ? sacc[nt][2] * scale : NEGINF;
            float v3 = (c0 + 1 <= rowB) ? sacc[nt][3] * scale : NEGINF;
            sacc[nt][0] = v0; sacc[nt][1] = v1;
            sacc[nt][2] = v2; sacc[nt][3] = v3;
            tmA = fmaxf(tmA, fmaxf(v0, v1));
            tmB = fmaxf(tmB, fmaxf(v2, v3));
        }
        tmA = fmaxf(tmA, __shfl_xor_sync(0xffffffffu, tmA, 1));
        tmA = fmaxf(tmA, __shfl_xor_sync(0xffffffffu, tmA, 2));
        tmB = fmaxf(tmB, __shfl_xor_sync(0xffffffffu, tmB, 1));
        tmB = fmaxf(tmB, __shfl_xor_sync(0xffffffffu, tmB, 2));

        const float mA2 = fmaxf(mA, tmA);
        const float mB2 = fmaxf(mB, tmB);
        const float aA = __expf(mA - mA2);
        const float aB = __expf(mB - mB2);

        // ---- P = exp(S - m), rounded tf32; row sums ----
        float sA = 0.f, sB = 0.f;
#pragma unroll
        for (int nt = 0; nt < 8; nt++) {
            float p0 = round_tf32(__expf(sacc[nt][0] - mA2));
            float p1 = round_tf32(__expf(sacc[nt][1] - mA2));
            float p2 = round_tf32(__expf(sacc[nt][2] - mB2));
            float p3 = round_tf32(__expf(sacc[nt][3] - mB2));
            sA += p0 + p1;
            sB += p2 + p3;
            int c = nt * 8 + qc * 2;
            *reinterpret_cast<float2*>(Ps + row0 * PST + c) = make_float2(p0, p1);
            *reinterpret_cast<float2*>(Ps + (row0 + 8) * PST + c) = make_float2(p2, p3);
        }
        sA += __shfl_xor_sync(0xffffffffu, sA, 1);
        sA += __shfl_xor_sync(0xffffffffu, sA, 2);
        sB += __shfl_xor_sync(0xffffffffu, sB, 1);
        sB += __shfl_xor_sync(0xffffffffu, sB, 2);

        lA = lA * aA + sA;
        lB = lB * aB + sB;
        mA = mA2;
        mB = mB2;
#pragma unroll
        for (int nt = 0; nt < 16; nt++) {
            o[nt][0] *= aA; o[nt][1] *= aA;
            o[nt][2] *= aB; o[nt][3] *= aB;
        }

        __syncthreads();

        if (kt + 1 < nkt) { load_K(kt + 1); CP_COMMIT(); }

        // ---- O += P @ V ----
#pragma unroll
        for (int ks = 0; ks < 8; ks++) {
            const int kq = ks * 8 + qc;
            unsigned af[4];
            af[0] = __float_as_uint(Ps[row0 * PST + kq]);
            af[1] = __float_as_uint(Ps[(row0 + 8) * PST + kq]);
            af[2] = __float_as_uint(Ps[row0 * PST + kq + 4]);
            af[3] = __float_as_uint(Ps[(row0 + 8) * PST + kq + 4]);
#pragma unroll
            for (int nt = 0; nt < 16; nt++) {
                unsigned bf[2];
                int n0 = nt * 8 + qr;
                bf[0] = __float_as_uint(Vs[kq * VST + n0]);
                bf[1] = __float_as_uint(Vs[(kq + 4) * VST + n0]);
                MMA_TF32(o[nt], af, bf);
            }
        }

        __syncthreads();

        if (kt + 1 < nkt) {
            load_V(kt + 1);
            CP_COMMIT();
            CP_WAIT0();
            __syncthreads();
        }
    }

    // ---- epilogue: O / l, rounded tf32 ----
    const float invA = 1.f / lA;
    const float invB = 1.f / lB;
    const long long baseA = ((long long)(bm + row0) * NH + h) * V_DIM;
    const long long baseB = ((long long)(bm + row0 + 8) * NH + h) * V_DIM;
#pragma unroll
    for (int nt = 0; nt < 16; nt++) {
        int c = nt * 8 + qc * 2;
        *reinterpret_cast<float2*>(attn + baseA + c) =
            make_float2(round_tf32(o[nt][0] * invA), round_tf32(o[nt][1] * invA));
        *reinterpret_cast<float2*>(attn + baseB + c) =
            make_float2(round_tf32(o[nt][2] * invB), round_tf32(o[nt][3] * invB));
    }
}

// ---------------------------------------------------------------------------
// Batched tf32 pre-rounding copy: 4 contiguous tensors in ONE launch.
// ---------------------------------------------------------------------------
struct CopyArgs {
    const float4* src[4];
    float4*       dst[4];
    int           prefix[5];
};

__global__ __launch_bounds__(256) void round_copy_all_kernel(CopyArgs a)
{
    const int b = blockIdx.x;
    int s = 0;
#pragma unroll
    for (int i = 1; i < 4; i++)
        if (b >= a.prefix[i]) s = i;
    const int chunk = b - a.prefix[s];
    const float4* in  = a.src[s] + (long long)chunk * 1024;
    float4*       out = a.dst[s] + (long long)chunk * 1024;

    const int i0 = threadIdx.x;
    float4 x = in[i0];
    float4 y = in[i0 + 256];
    float4 z = in[i0 + 512];
    float4 w = in[i0 + 768];
    x.x = round_tf32(x.x); x.y = round_tf32(x.y);
    x.z = round_tf32(x.z); x.w = round_tf32(x.w);
    y.x = round_tf32(y.x); y.y = round_tf32(y.y);
    y.z = round_tf32(y.z); y.w = round_tf32(y.w);
    z.x = round_tf32(z.x); z.y = round_tf32(z.y);
    z.z = round_tf32(z.z); z.w = round_tf32(z.w);
    w.x = round_tf32(w.x); w.y = round_tf32(w.y);
    w.z = round_tf32(w.z); w.w = round_tf32(w.w);
    out[i0]       = x;
    out[i0 + 256] = y;
    out[i0 + 512] = z;
    out[i0 + 768] = w;
}

// ---------------------------------------------------------------------------
// Strided tf32 rounding copy: src [rows, ncols] (ld ncols) ->
// dst rows with ld NCAT at column offset coff. ncols % 4 == 0, coff % 4 == 0.
// Used to build the concatenated weight matrix w_cat = [w_qa | w_kva].
// ---------------------------------------------------------------------------
__global__ __launch_bounds__(256) void round_copy_strided_kernel(
    const float4* __restrict__ src, float4* __restrict__ dst_base,
    int rows, int ncols4, int ldd4)
{
    long long total = (long long)rows * ncols4;
    for (long long i = (long long)blockIdx.x * blockDim.x + threadIdx.x;
         i < total; i += (long long)gridDim.x * blockDim.x) {
        int r  = (int)(i / ncols4);
        int c4 = (int)(i % ncols4);
        float4 v = src[(long long)r * ncols4 + c4];
        v.x = round_tf32(v.x); v.y = round_tf32(v.y);
        v.z = round_tf32(v.z); v.w = round_tf32(v.w);
        dst_base[(long long)r * ldd4 + c4] = v;
    }
}

// ---------------------------------------------------------------------------
// RMSNorm: one block per row; output rounded to tf32
// ---------------------------------------------------------------------------
__global__ __launch_bounds__(256) void rmsnorm_kernel(
    const float* __restrict__ in, int ldin,
    float* __restrict__ out, int ldout,
    const float* __restrict__ w, int cols)
{
    const int r = blockIdx.x;
    const float* x = in + (long long)r * ldin;
    float ss = 0.f;
    for (int c = threadIdx.x; c < cols; c += blockDim.x) {
        float v = x[c];
        ss += v * v;
    }
    __shared__ float sh[256];
    sh[threadIdx.x] = ss;
    __syncthreads();
    for (int s = 128; s > 0; s >>= 1) {
        if (threadIdx.x < s) sh[threadIdx.x] += sh[threadIdx.x + s];
        __syncthreads();
    }
    float scale = rsqrtf(sh[0] / (float)cols + EPSV);
    for (int c = threadIdx.x; c < cols; c += blockDim.x)
        out[(long long)r * ldout + c] = round_tf32(x[c] * scale * w[c]);
}

// ---------------------------------------------------------------------------
// RoPE (interleaved): rotates q rope dims (rounded), emits rounded k_rope.
// kvc points at the kv_c block (ld = ldkvc); k_rope = kvc[:, KV_LORA:].
// ---------------------------------------------------------------------------
__global__ __launch_bounds__(512) void rope_kernel(
    float* __restrict__ q, const float* __restrict__ kvc, int ldkvc,
    float* __restrict__ krope, const int* __restrict__ positions)
{
    const int s = blockIdx.x;
    const int t = threadIdx.x;
    const int h = t >> 5;
    const int i = t & 31;

    float pos = (float)positions[s];
    float inv = powf(10000.0f, -(2.0f * (float)i) / (float)ROPE);
    float ang = pos * inv;
    float sn, cs;
    sincosf(ang, &sn, &cs);

    float* qp = q + ((long long)s * NH + h) * QK + NOPE + 2 * i;
    float x1 = qp[0], x2 = qp[1];
    qp[0] = round_tf32(x1 * cs - x2 * sn);
    qp[1] = round_tf32(x2 * cs + x1 * sn);

    if (h == 0) {
        const float* kp = kvc + (long long)s * ldkvc + KV_LORA + 2 * i;
        float y1 = kp[0], y2 = kp[1];
        krope[(long long)s * ROPE + 2 * i]     = round_tf32(y1 * cs - y2 * sn);
        krope[(long long)s * ROPE + 2 * i + 1] = round_tf32(y2 * cs + y1 * sn);
    }
}

// ---------------------------------------------------------------------------
// Host launcher
// ---------------------------------------------------------------------------
static inline void* sym_addr(const void* symbol)
{
    void* p = nullptr;
    cudaGetSymbolAddress(&p, symbol);
    return p;
}

extern "C" void kernel_launch(void* const* d_in, const int* in_sizes, int n_in,
                              void* d_out, int out_size)
{
    const float* hidden  = (const float*)d_in[0];
    const float* w_qa    = (const float*)d_in[1];
    const float* qa_ln_w = (const float*)d_in[2];
    const float* w_qb    = (const float*)d_in[3];
    const float* w_kva   = (const float*)d_in[4];
    const float* kva_ln_w= (const float*)d_in[5];
    const float* w_kvb   = (const float*)d_in[6];
    const float* w_o     = (const float*)d_in[7];
    const int*   positions = (const int*)d_in[8];
    float* out = (float*)d_out;

    float* qc     = (float*)sym_addr(g_qc);
    float* qcat   = (float*)sym_addr(g_qcat);
    float* kvlat  = (float*)sym_addr(g_kvlat);
    float* kv     = (float*)sym_addr(g_kv);
    float* krope  = (float*)sym_addr(g_krope);
    float* q      = (float*)sym_addr(g_q);
    float* attn   = (float*)sym_addr(g_attn);

    float* hid_r  = (float*)sym_addr(g_hid_r);
    float* wcat_r = (float*)sym_addr(g_wcat_r);
    float* wqb_r  = (float*)sym_addr(g_wqb_r);
    float* wkvb_r = (float*)sym_addr(g_wkvb_r);
    float* wo_r   = (float*)sym_addr(g_wo_r);

    const dim3 blk(256);

    cudaFuncSetAttribute(mma_gemm<false>,
                         cudaFuncAttributeMaxDynamicSharedMemorySize, (int)GEMM_SMEM);
    cudaFuncSetAttribute(mma_gemm<true>,
                         cudaFuncAttributeMaxDynamicSharedMemorySize, (int)GEMM_SMEM);
    cudaFuncSetAttribute(flash_attn_kernel,
                         cudaFuncAttributeMaxDynamicSharedMemorySize, FLASH_SMEM);

    // 0a. tf32-round contiguous inputs (hidden, w_qb, w_kvb, w_o) — one launch
    {
        CopyArgs a;
        const float* srcs[4] = { hidden, w_qb, w_kvb, w_o };
        float* dsts[4]       = { hid_r, wqb_r, wkvb_r, wo_r };
        long long ns[4] = {
            (long long)S * HIDDEN,
            (long long)Q_LORA * NH * QK,
            (long long)KV_LORA * NH * KVD,
            (long long)NH * V_DIM * HIDDEN };
        int pre = 0;
        for (int i = 0; i < 4; i++) {
            a.src[i] = (const float4*)srcs[i];
            a.dst[i] = (float4*)dsts[i];
            a.prefix[i] = pre;
            pre += (int)(ns[i] / 4 / 1024);   // all divisible by 4096
        }
        a.prefix[4] = pre;
        round_copy_all_kernel<<<pre, blk>>>(a);
    }
    // 0b. build w_cat = [w_qa | w_kva] (tf32-rounded, strided)
    round_copy_strided_kernel<<<592, blk>>>(
        (const float4*)w_qa, (float4*)wcat_r,
        HIDDEN, Q_LORA / 4, NCAT / 4);
    round_copy_strided_kernel<<<592, blk>>>(
        (const float4*)w_kva, (float4*)(wcat_r + Q_LORA),
        HIDDEN, (KV_LORA + ROPE) / 4, NCAT / 4);

    // 1. fused: [q_c_raw | kv_c] = hidden @ w_cat   [2048,2112] K=2048
    mma_gemm<false><<<dim3((NCAT + BNv - 1) / BNv, S / BM, 1), blk, GEMM_SMEM>>>(
        hid_r, HIDDEN, wcat_r, NCAT, qcat, NCAT,
        S, NCAT, HIDDEN, 1.0f);

    // 2. rmsnorm(q_c): qcat[:, :1536] -> qc (rounded)
    rmsnorm_kernel<<<S, blk>>>(qcat, NCAT, qc, Q_LORA, qa_ln_w, Q_LORA);

    // 3. q = q_c @ w_qb                     [2048,3072] K=1536, rounded output
    mma_gemm<true><<<dim3((NH * QK) / BNv, S / BM, 1), blk, GEMM_SMEM>>>(
        qc, Q_LORA, wqb_r, NH * QK, q, NH * QK,
        S, NH * QK, Q_LORA, 1.0f);

    // 4. kv_lat = rmsnorm(qcat[:, 1536:2048]) (rounded)
    rmsnorm_kernel<<<S, blk>>>(qcat + Q_LORA, NCAT, kvlat, KV_LORA, kva_ln_w, KV_LORA);

    // 5. kv = kv_lat @ w_kvb                [2048,4096] K=512, rounded output
    mma_gemm<true><<<dim3((NH * KVD) / BNv, S / BM, 1), blk, GEMM_SMEM>>>(
        kvlat, KV_LORA, wkvb_r, NH * KVD, kv, NH * KVD,
        S, NH * KVD, KV_LORA, 1.0f);

    // 6. RoPE (kv_c block lives at qcat + Q_LORA with ld NCAT)
    rope_kernel<<<S, 512>>>(q, qcat + Q_LORA, NCAT, krope, positions);

    // 7. fused causal flash attention -> attn (tf32-rounded)
    flash_attn_kernel<<<dim3(S / 128, NH), blk, FLASH_SMEM>>>(q, kv, krope, attn);

    // 8. out = attn @ w_o                   [2048,2048] K=2048
    mma_gemm<false><<<dim3(HIDDEN / BNv, S / BM, 1), blk, GEMM_SMEM>>>(
        attn, NH * V_DIM, wo_r, HIDDEN, out, HIDDEN,
        S, HIDDEN, NH * V_DIM, 1.0f);
}

// round 16
// speedup vs baseline: 1.2235x; 1.0457x over previous
#include <cuda_runtime.h>
#include <cuda_bf16.h>
#include <math.h>

// ---------------------------------------------------------------------------
// Problem constants
// ---------------------------------------------------------------------------
#define S 2048
#define HIDDEN 2048
#define Q_LORA 1536
#define KV_LORA 512
#define NOPE 128
#define ROPE 64
#define V_DIM 128
#define NH 16
#define QK 192          // NOPE + ROPE
#define KVD 256         // NOPE + V_DIM
#define EPSV 1e-6f
#define NCAT 2112       // Q_LORA + KV_LORA + ROPE (fused GEMM1+kv_c width)

// ---------------------------------------------------------------------------
// Scratch (static device globals)
// ---------------------------------------------------------------------------
__device__ float g_qc    [(size_t)S * Q_LORA];        // rmsnorm'd q_c
__device__ float g_qcat  [(size_t)S * NCAT];          // fused GEMM1+kv_c output
__device__ float g_kvlat [(size_t)S * KV_LORA];
__device__ float g_kv    [(size_t)S * NH * KVD];
__device__ float g_krope [(size_t)S * ROPE];
__device__ float g_q     [(size_t)S * NH * QK];
__device__ float g_attn  [(size_t)S * NH * V_DIM];

// tf32-rounded copies of external inputs
__device__ float g_hid_r [(size_t)S * HIDDEN];
__device__ float g_wcat_r[(size_t)HIDDEN * NCAT];     // [w_qa | w_kva] col-concat
__device__ float g_wqb_r [(size_t)Q_LORA * NH * QK];
__device__ float g_wkvb_r[(size_t)KV_LORA * NH * KVD];
__device__ float g_wo_r  [(size_t)NH * V_DIM * HIDDEN];

// ---------------------------------------------------------------------------
// tf32 helpers
// ---------------------------------------------------------------------------
__device__ __forceinline__ unsigned cvt_tf32(float x) {
    unsigned r;
    asm("cvt.rna.tf32.f32 %0, %1;" : "=r"(r) : "f"(x));
    return r;
}
__device__ __forceinline__ float round_tf32(float x) {
    return __uint_as_float(cvt_tf32(x));
}

__device__ __forceinline__ void cp_async16(float* dst, const float* src, bool pred) {
    unsigned d = (unsigned)__cvta_generic_to_shared(dst);
    int sz = pred ? 16 : 0;
    asm volatile("cp.async.cg.shared.global [%0], [%1], 16, %2;"
                 :: "r"(d), "l"(src), "r"(sz));
}

#define CP_COMMIT() asm volatile("cp.async.commit_group;")
#define CP_WAIT0()  asm volatile("cp.async.wait_group 0;")
#define CP_WAIT1()  asm volatile("cp.async.wait_group 1;")

#define MMA_TF32(d, a, b)                                                     \
    asm volatile(                                                             \
        "mma.sync.aligned.m16n8k8.row.col.f32.tf32.tf32.f32 "                 \
        "{%0,%1,%2,%3},{%4,%5,%6,%7},{%8,%9},{%0,%1,%2,%3};"                  \
        : "+f"((d)[0]), "+f"((d)[1]), "+f"((d)[2]), "+f"((d)[3])              \
        : "r"((a)[0]), "r"((a)[1]), "r"((a)[2]), "r"((a)[3]),                 \
          "r"((b)[0]), "r"((b)[1]))

// ldmatrix x4: loads 4 8x8-b16 matrices (= 4 tf32 8x4 fragments) in one op.
// Lanes 0-7 address matrix 0, 8-15 m1, 16-23 m2, 24-31 m3.
#define LDSM_X4(R0, R1, R2, R3, ADDR)                                         \
    asm volatile("ldmatrix.sync.aligned.m8n8.x4.shared.b16 {%0,%1,%2,%3}, [%4];" \
        : "=r"(R0), "=r"(R1), "=r"(R2), "=r"(R3) : "r"(ADDR))

__device__ __forceinline__ unsigned smem_u32(const float* p) {
    return (unsigned)__cvta_generic_to_shared(p);
}

// ---------------------------------------------------------------------------
// tf32 tensor-core GEMM: C[M,N] = alpha * A[M,K] @ B, row-major.
// A fragments loaded via ldmatrix.x4 (row-major smem, conflict-free);
// B fragments via scalar LDS (k-major smem, no tf32 ldmatrix.trans).
// CTA tile 128 x 128 x 32, 256 threads = 8 warps (4m x 2n), warp tile 32x64.
// 3-stage cp.async pipeline, 2 CTAs/SM.
// ---------------------------------------------------------------------------
#define BM 128
#define BK 32
#define BNv 128
#define AST 36                   // smem stride for A tiles
#define ASTG (BM * AST)          // 4608 floats per A stage
#define NSTAGE 3
#define BST (BNv + 8)            // k-major B smem stride
#define BSTG (BK * BST)
#define GEMM_SMEM ((size_t)NSTAGE * (ASTG + BSTG) * 4)   // 107,520 B

template <bool ROUND_OUT>
__global__ __launch_bounds__(256, 2) void mma_gemm(
    const float* __restrict__ A, int lda,
    const float* __restrict__ B, int ldb,
    float* __restrict__ C, int ldc,
    int M, int N, int K, float alpha)
{
    constexpr int NT = BNv / 16;                   // 8 n-tiles per warp

    const int bm = blockIdx.y * BM;
    const int bn = blockIdx.x * BNv;

    const int niter = K / BK;

    extern __shared__ float smem[];
    float* As = smem;                     // [NSTAGE][ASTG]
    float* Bs = smem + NSTAGE * ASTG;     // [NSTAGE][BSTG]

    const int tid  = threadIdx.x;
    const int lane = tid & 31;
    const int wid  = tid >> 5;
    const int wm   = wid & 3;             // warp row block (32 rows)
    const int wn   = wid >> 2;            // warp col block (64 cols)

    // ldmatrix A-fragment addressing: matrices {r+0,c0},{r+8,c0},{r+0,c4},{r+8,c4}
    const int lrow = lane & 7;
    const int lsel = lane >> 3;
    const int arow = 8 * (lsel & 1) + lrow;       // row offset within 16
    const int acol = 4 * (lsel >> 1);             // tf32 col offset

    float acc[2][NT][4];
#pragma unroll
    for (int mt = 0; mt < 2; mt++)
#pragma unroll
        for (int nt = 0; nt < NT; nt++)
#pragma unroll
            for (int i = 0; i < 4; i++) acc[mt][nt][i] = 0.f;

    auto load_A = [&](int stage, int k0) {
#pragma unroll
        for (int p = 0; p < 4; p++) {
            int lin = p * 256 + tid;
            int r = lin >> 3, cq = lin & 7;
            cp_async16(As + stage * ASTG + r * AST + cq * 4,
                       A + (long long)(bm + r) * lda + k0 + cq * 4, true);
        }
    };
    auto load_B = [&](int stage, int k0) {
#pragma unroll
        for (int p = 0; p < BNv / 32; p++) {
            int lin = p * 256 + tid;
            int r = lin / (BNv / 4);
            int cq = lin % (BNv / 4);
            bool pred = (bn + cq * 4) < N;
            cp_async16(Bs + stage * BSTG + r * BST + cq * 4,
                       B + (long long)(k0 + r) * ldb + bn + cq * 4, pred);
        }
    };

    // ---- pipeline prologue ----
    load_A(0, 0); load_B(0, 0); CP_COMMIT();
    if (niter > 1) { load_A(1, BK); load_B(1, BK); CP_COMMIT(); }

    // ---- main loop ----
    for (int it = 0; it < niter; it++) {
        if (it + 1 < niter) CP_WAIT1(); else CP_WAIT0();
        __syncthreads();

        if (it + 2 < niter) {
            int stg = (it + 2) % NSTAGE;
            load_A(stg, (it + 2) * BK);
            load_B(stg, (it + 2) * BK);
            CP_COMMIT();
        }

        const int cur = it % NSTAGE;
        const float* Asb = As + cur * ASTG;
        const float* Bsb = Bs + cur * BSTG;

#pragma unroll
        for (int ks = 0; ks < BK / 8; ks++) {
            const int kq = ks * 8 + (lane & 3);
            unsigned af[2][4];
#pragma unroll
            for (int mt = 0; mt < 2; mt++) {
                unsigned addr = smem_u32(
                    Asb + (wm * 32 + mt * 16 + arow) * AST + ks * 8 + acol);
                LDSM_X4(af[mt][0], af[mt][1], af[mt][2], af[mt][3], addr);
            }
            unsigned bf[NT][2];
#pragma unroll
            for (int nt = 0; nt < NT; nt++) {
                int n0 = wn * 64 + nt * 8 + (lane >> 2);
                bf[nt][0] = __float_as_uint(Bsb[kq * BST + n0]);
                bf[nt][1] = __float_as_uint(Bsb[(kq + 4) * BST + n0]);
            }
#pragma unroll
            for (int mt = 0; mt < 2; mt++)
#pragma unroll
                for (int nt = 0; nt < NT; nt++)
                    MMA_TF32(acc[mt][nt], af[mt], bf[nt]);
        }
    }

    // ---- epilogue ----
#pragma unroll
    for (int mt = 0; mt < 2; mt++) {
        int r0 = bm + wm * 32 + mt * 16 + (lane >> 2);
#pragma unroll
        for (int nt = 0; nt < NT; nt++) {
            int c0 = bn + wn * 64 + nt * 8 + (lane & 3) * 2;
            if (c0 < N) {
                float x0 = acc[mt][nt][0] * alpha, x1 = acc[mt][nt][1] * alpha;
                float x2 = acc[mt][nt][2] * alpha, x3 = acc[mt][nt][3] * alpha;
                if (ROUND_OUT) {
                    x0 = round_tf32(x0); x1 = round_tf32(x1);
                    x2 = round_tf32(x2); x3 = round_tf32(x3);
                }
                *reinterpret_cast<float2*>(C + (long long)r0 * ldc + c0) =
                    make_float2(x0, x1);
                *reinterpret_cast<float2*>(C + (long long)(r0 + 8) * ldc + c0) =
                    make_float2(x2, x3);
            }
        }
    }
}

// ---------------------------------------------------------------------------
// Fused causal flash attention (tf32 mma, online softmax). R9 structure.
// Q/P A-fragments and K B-fragments via ldmatrix (row-major, conflict-free);
// V stays scalar LDS (k-major).
// smem: Q 128x192(s196) | K 64x192(s196) | V 64x128(s136) | P 128x64(s68)
// ---------------------------------------------------------------------------
#define QST 196
#define KST 196
#define VST 136
#define PST 68
#define FL_Q 0
#define FL_K 25088
#define FL_V 37632
#define FL_P 46336
#define FLASH_SMEM ((46336 + 128 * PST) * 4)   // 220,160 bytes
#define NEGINF (-3.0e38f)

__global__ __launch_bounds__(256) void flash_attn_kernel(
    const float* __restrict__ q,
    const float* __restrict__ kv,
    const float* __restrict__ krope,
    float* __restrict__ attn)
{
    const int qt  = (int)gridDim.x - 1 - (int)blockIdx.x;  // heavy tiles first
    const int h   = blockIdx.y;
    const int bm  = qt * 128;
    const int nkt = bm / 64 + 2;
    const float scale = 0.07216878364870322f;  // 1/sqrt(192)

    extern __shared__ float sm[];
    float* Qs = sm + FL_Q;
    float* Ks = sm + FL_K;
    float* Vs = sm + FL_V;
    float* Ps = sm + FL_P;

    const int tid  = threadIdx.x;
    const int lane = tid & 31;
    const int wid  = tid >> 5;
    const int qr   = lane >> 2;
    const int qc   = lane & 3;
    const int row0 = wid * 16 + qr;

    // ldmatrix addressing
    const int lrow = lane & 7;
    const int lsel = lane >> 3;
    const int arow = 8 * (lsel & 1) + lrow;     // A-frag: {r0,c0},{r8,c0},{r0,c4},{r8,c4}
    const int acol = 4 * (lsel >> 1);
    const int krow = 8 * (lsel >> 1) + lrow;    // K-frag: {n0,c0},{n0,c4},{n8,c0},{n8,c4}
    const int kcol = 4 * (lsel & 1);

    auto load_K = [&](int kt) {
        int t0 = kt * 64;
#pragma unroll
        for (int p = 0; p < 12; p++) {
            int lin = p * 256 + tid;
            int r = lin / 48, seg = lin % 48;
            const float* src = (seg < 32)
                ? kv + ((long long)(t0 + r) * NH + h) * KVD + seg * 4
                : krope + (long long)(t0 + r) * ROPE + (seg - 32) * 4;
            cp_async16(Ks + r * KST + seg * 4, src, true);
        }
    };
    auto load_V = [&](int kt) {
        int t0 = kt * 64;
#pragma unroll
        for (int p = 0; p < 8; p++) {
            int lin = p * 256 + tid;
            int r = lin / 32, c = lin % 32;
            cp_async16(Vs + r * VST + c * 4,
                       kv + ((long long)(t0 + r) * NH + h) * KVD + NOPE + c * 4,
                       true);
        }
    };

    // ---- prologue: Q tile + first K/V tile ----
#pragma unroll
    for (int p = 0; p < 24; p++) {
        int lin = p * 256 + tid;
        int r = lin / 48, seg = lin % 48;
        cp_async16(Qs + r * QST + seg * 4,
                   q + ((long long)(bm + r) * NH + h) * QK + seg * 4, true);
    }
    load_K(0);
    load_V(0);
    CP_COMMIT();
    CP_WAIT0();
    __syncthreads();

    float o[16][4];
#pragma unroll
    for (int nt = 0; nt < 16; nt++)
#pragma unroll
        for (int i = 0; i < 4; i++) o[nt][i] = 0.f;
    float mA = NEGINF, mB = NEGINF, lA = 0.f, lB = 0.f;

    for (int kt = 0; kt < nkt; kt++) {
        const int t0 = kt * 64;

        // ---- S = Q K^T (16x64 per warp, K=192) ----
        float sacc[8][4];
#pragma unroll
        for (int nt = 0; nt < 8; nt++)
#pragma unroll
            for (int i = 0; i < 4; i++) sacc[nt][i] = 0.f;

#pragma unroll
        for (int ks = 0; ks < 24; ks++) {
            unsigned af[4];
            {
                unsigned addr = smem_u32(
                    Qs + (wid * 16 + arow) * QST + ks * 8 + acol);
                LDSM_X4(af[0], af[1], af[2], af[3], addr);
            }
            unsigned bf[8][2];
#pragma unroll
            for (int p = 0; p < 8; p += 2) {
                unsigned addr = smem_u32(
                    Ks + (p * 8 + krow) * KST + ks * 8 + kcol);
                LDSM_X4(bf[p][0], bf[p][1], bf[p + 1][0], bf[p + 1][1], addr);
            }
#pragma unroll
            for (int nt = 0; nt < 8; nt++)
                MMA_TF32(sacc[nt], af, bf[nt]);
        }

        // ---- scale + causal mask + tile row-max ----
        const int rowA = bm + row0;
        const int rowB = rowA + 8;
        float tmA = NEGINF, tmB = NEGINF;
#pragma unroll
        for (int nt = 0; nt < 8; nt++) {
            int c0 = t0 + nt * 8 + qc * 2;
            float v0 = (c0     <= rowA) ? sacc[nt][0] * scale : NEGINF;
            float v1 = (c0 + 1 <= rowA) ? sacc[nt][1] * scale : NEGINF;
            float v2 = (c0     <= rowB) ? sacc[nt][2] * scale : NEGINF;
            float v3 = (c0 + 1 <= rowB) ? sacc[nt][3] * scale : NEGINF;
            sacc[nt][0] = v0; sacc[nt][1] = v1;
            sacc[nt][2] = v2; sacc[nt][3] = v3;
            tmA = fmaxf(tmA, fmaxf(v0, v1));
            tmB = fmaxf(tmB, fmaxf(v2, v3));
        }
        tmA = fmaxf(tmA, __shfl_xor_sync(0xffffffffu, tmA, 1));
        tmA = fmaxf(tmA, __shfl_xor_sync(0xffffffffu, tmA, 2));
        tmB = fmaxf(tmB, __shfl_xor_sync(0xffffffffu, tmB, 1));
        tmB = fmaxf(tmB, __shfl_xor_sync(0xffffffffu, tmB, 2));

        const float mA2 = fmaxf(mA, tmA);
        const float mB2 = fmaxf(mB, tmB);
        const float aA = __expf(mA - mA2);
        const float aB = __expf(mB - mB2);

        // ---- P = exp(S - m), rounded tf32; row sums ----
        float sA = 0.f, sB = 0.f;
#pragma unroll
        for (int nt = 0; nt < 8; nt++) {
            float p0 = round_tf32(__expf(sacc[nt][0] - mA2));
            float p1 = round_tf32(__expf(sacc[nt][1] - mA2));
            float p2 = round_tf32(__expf(sacc[nt][2] - mB2));
            float p3 = round_tf32(__expf(sacc[nt][3] - mB2));
            sA += p0 + p1;
            sB += p2 + p3;
            int c = nt * 8 + qc * 2;
            *reinterpret_cast<float2*>(Ps + row0 * PST + c) = make_float2(p0, p1);
            *reinterpret_cast<float2*>(Ps + (row0 + 8) * PST + c) = make_float2(p2, p3);
        }
        sA += __shfl_xor_sync(0xffffffffu, sA, 1);
        sA += __shfl_xor_sync(0xffffffffu, sA, 2);
        sB += __shfl_xor_sync(0xffffffffu, sB, 1);
        sB += __shfl_xor_sync(0xffffffffu, sB, 2);

        lA = lA * aA + sA;
        lB = lB * aB + sB;
        mA = mA2;
        mB = mB2;
#pragma unroll
        for (int nt = 0; nt < 16; nt++) {
            o[nt][0] *= aA; o[nt][1] *= aA;
            o[nt][2] *= aB; o[nt][3] *= aB;
        }

        __syncthreads();   // all warps done with Ks, Ps written

        if (kt + 1 < nkt) { load_K(kt + 1); CP_COMMIT(); }

        // ---- O += P @ V (16x128 per warp, K=64) ----
#pragma unroll
        for (int ks = 0; ks < 8; ks++) {
            const int kq = ks * 8 + qc;
            unsigned af[4];
            {
                unsigned addr = smem_u32(
                    Ps + (wid * 16 + arow) * PST + ks * 8 + acol);
                LDSM_X4(af[0], af[1], af[2], af[3], addr);
            }
#pragma unroll
            for (int nt = 0; nt < 16; nt++) {
                unsigned bf[2];
                int n0 = nt * 8 + qr;
                bf[0] = __float_as_uint(Vs[kq * VST + n0]);
                bf[1] = __float_as_uint(Vs[(kq + 4) * VST + n0]);
                MMA_TF32(o[nt], af, bf);
            }
        }

        __syncthreads();   // all warps done with Vs, Ps

        if (kt + 1 < nkt) {
            load_V(kt + 1);
            CP_COMMIT();
            CP_WAIT0();
            __syncthreads();
        }
    }

    // ---- epilogue: O / l, rounded tf32 ----
    const float invA = 1.f / lA;
    const float invB = 1.f / lB;
    const long long baseA = ((long long)(bm + row0) * NH + h) * V_DIM;
    const long long baseB = ((long long)(bm + row0 + 8) * NH + h) * V_DIM;
#pragma unroll
    for (int nt = 0; nt < 16; nt++) {
        int c = nt * 8 + qc * 2;
        *reinterpret_cast<float2*>(attn + baseA + c) =
            make_float2(round_tf32(o[nt][0] * invA), round_tf32(o[nt][1] * invA));
        *reinterpret_cast<float2*>(attn + baseB + c) =
            make_float2(round_tf32(o[nt][2] * invB), round_tf32(o[nt][3] * invB));
    }
}

// ---------------------------------------------------------------------------
// Batched tf32 pre-rounding copy: 4 contiguous tensors in ONE launch.
// ---------------------------------------------------------------------------
struct CopyArgs {
    const float4* src[4];
    float4*       dst[4];
    int           prefix[5];
};

__global__ __launch_bounds__(256) void round_copy_all_kernel(CopyArgs a)
{
    const int b = blockIdx.x;
    int s = 0;
#pragma unroll
    for (int i = 1; i < 4; i++)
        if (b >= a.prefix[i]) s = i;
    const int chunk = b - a.prefix[s];
    const float4* in  = a.src[s] + (long long)chunk * 1024;
    float4*       out = a.dst[s] + (long long)chunk * 1024;

    const int i0 = threadIdx.x;
    float4 x = in[i0];
    float4 y = in[i0 + 256];
    float4 z = in[i0 + 512];
    float4 w = in[i0 + 768];
    x.x = round_tf32(x.x); x.y = round_tf32(x.y);
    x.z = round_tf32(x.z); x.w = round_tf32(x.w);
    y.x = round_tf32(y.x); y.y = round_tf32(y.y);
    y.z = round_tf32(y.z); y.w = round_tf32(y.w);
    z.x = round_tf32(z.x); z.y = round_tf32(z.y);
    z.z = round_tf32(z.z); z.w = round_tf32(z.w);
    w.x = round_tf32(w.x); w.y = round_tf32(w.y);
    w.z = round_tf32(w.z); w.w = round_tf32(w.w);
    out[i0]       = x;
    out[i0 + 256] = y;
    out[i0 + 512] = z;
    out[i0 + 768] = w;
}

// ---------------------------------------------------------------------------
// Strided tf32 rounding copy: builds w_cat = [w_qa | w_kva].
// ---------------------------------------------------------------------------
__global__ __launch_bounds__(256) void round_copy_strided_kernel(
    const float4* __restrict__ src, float4* __restrict__ dst_base,
    int rows, int ncols4, int ldd4)
{
    long long total = (long long)rows * ncols4;
    for (long long i = (long long)blockIdx.x * blockDim.x + threadIdx.x;
         i < total; i += (long long)gridDim.x * blockDim.x) {
        int r  = (int)(i / ncols4);
        int c4 = (int)(i % ncols4);
        float4 v = src[(long long)r * ncols4 + c4];
        v.x = round_tf32(v.x); v.y = round_tf32(v.y);
        v.z = round_tf32(v.z); v.w = round_tf32(v.w);
        dst_base[(long long)r * ldd4 + c4] = v;
    }
}

// ---------------------------------------------------------------------------
// RMSNorm: one block per row; output rounded to tf32
// ---------------------------------------------------------------------------
__global__ __launch_bounds__(256) void rmsnorm_kernel(
    const float* __restrict__ in, int ldin,
    float* __restrict__ out, int ldout,
    const float* __restrict__ w, int cols)
{
    const int r = blockIdx.x;
    const float* x = in + (long long)r * ldin;
    float ss = 0.f;
    for (int c = threadIdx.x; c < cols; c += blockDim.x) {
        float v = x[c];
        ss += v * v;
    }
    __shared__ float sh[256];
    sh[threadIdx.x] = ss;
    __syncthreads();
    for (int s = 128; s > 0; s >>= 1) {
        if (threadIdx.x < s) sh[threadIdx.x] += sh[threadIdx.x + s];
        __syncthreads();
    }
    float scale = rsqrtf(sh[0] / (float)cols + EPSV);
    for (int c = threadIdx.x; c < cols; c += blockDim.x)
        out[(long long)r * ldout + c] = round_tf32(x[c] * scale * w[c]);
}

// ---------------------------------------------------------------------------
// RoPE (interleaved): rotates q rope dims (rounded), emits rounded k_rope.
// kvc points at the kv_c block (ld = ldkvc); k_rope = kvc[:, KV_LORA:].
// ---------------------------------------------------------------------------
__global__ __launch_bounds__(512) void rope_kernel(
    float* __restrict__ q, const float* __restrict__ kvc, int ldkvc,
    float* __restrict__ krope, const int* __restrict__ positions)
{
    const int s = blockIdx.x;
    const int t = threadIdx.x;
    const int h = t >> 5;
    const int i = t & 31;

    float pos = (float)positions[s];
    float inv = powf(10000.0f, -(2.0f * (float)i) / (float)ROPE);
    float ang = pos * inv;
    float sn, cs;
    sincosf(ang, &sn, &cs);

    float* qp = q + ((long long)s * NH + h) * QK + NOPE + 2 * i;
    float x1 = qp[0], x2 = qp[1];
    qp[0] = round_tf32(x1 * cs - x2 * sn);
    qp[1] = round_tf32(x2 * cs + x1 * sn);

    if (h == 0) {
        const float* kp = kvc + (long long)s * ldkvc + KV_LORA + 2 * i;
        float y1 = kp[0], y2 = kp[1];
        krope[(long long)s * ROPE + 2 * i]     = round_tf32(y1 * cs - y2 * sn);
        krope[(long long)s * ROPE + 2 * i + 1] = round_tf32(y2 * cs + y1 * sn);
    }
}

// ---------------------------------------------------------------------------
// Host launcher
// ---------------------------------------------------------------------------
static inline void* sym_addr(const void* symbol)
{
    void* p = nullptr;
    cudaGetSymbolAddress(&p, symbol);
    return p;
}

extern "C" void kernel_launch(void* const* d_in, const int* in_sizes, int n_in,
                              void* d_out, int out_size)
{
    const float* hidden  = (const float*)d_in[0];
    const float* w_qa    = (const float*)d_in[1];
    const float* qa_ln_w = (const float*)d_in[2];
    const float* w_qb    = (const float*)d_in[3];
    const float* w_kva   = (const float*)d_in[4];
    const float* kva_ln_w= (const float*)d_in[5];
    const float* w_kvb   = (const float*)d_in[6];
    const float* w_o     = (const float*)d_in[7];
    const int*   positions = (const int*)d_in[8];
    float* out = (float*)d_out;

    float* qc     = (float*)sym_addr(g_qc);
    float* qcat   = (float*)sym_addr(g_qcat);
    float* kvlat  = (float*)sym_addr(g_kvlat);
    float* kv     = (float*)sym_addr(g_kv);
    float* krope  = (float*)sym_addr(g_krope);
    float* q      = (float*)sym_addr(g_q);
    float* attn   = (float*)sym_addr(g_attn);

    float* hid_r  = (float*)sym_addr(g_hid_r);
    float* wcat_r = (float*)sym_addr(g_wcat_r);
    float* wqb_r  = (float*)sym_addr(g_wqb_r);
    float* wkvb_r = (float*)sym_addr(g_wkvb_r);
    float* wo_r   = (float*)sym_addr(g_wo_r);

    const dim3 blk(256);

    cudaFuncSetAttribute(mma_gemm<false>,
                         cudaFuncAttributeMaxDynamicSharedMemorySize, (int)GEMM_SMEM);
    cudaFuncSetAttribute(mma_gemm<true>,
                         cudaFuncAttributeMaxDynamicSharedMemorySize, (int)GEMM_SMEM);
    cudaFuncSetAttribute(flash_attn_kernel,
                         cudaFuncAttributeMaxDynamicSharedMemorySize, FLASH_SMEM);

    // 0a. tf32-round contiguous inputs (hidden, w_qb, w_kvb, w_o) — one launch
    {
        CopyArgs a;
        const float* srcs[4] = { hidden, w_qb, w_kvb, w_o };
        float* dsts[4]       = { hid_r, wqb_r, wkvb_r, wo_r };
        long long ns[4] = {
            (long long)S * HIDDEN,
            (long long)Q_LORA * NH * QK,
            (long long)KV_LORA * NH * KVD,
            (long long)NH * V_DIM * HIDDEN };
        int pre = 0;
        for (int i = 0; i < 4; i++) {
            a.src[i] = (const float4*)srcs[i];
            a.dst[i] = (float4*)dsts[i];
            a.prefix[i] = pre;
            pre += (int)(ns[i] / 4 / 1024);
        }
        a.prefix[4] = pre;
        round_copy_all_kernel<<<pre, blk>>>(a);
    }
    // 0b. build w_cat = [w_qa | w_kva] (tf32-rounded, strided)
    round_copy_strided_kernel<<<592, blk>>>(
        (const float4*)w_qa, (float4*)wcat_r,
        HIDDEN, Q_LORA / 4, NCAT / 4);
    round_copy_strided_kernel<<<592, blk>>>(
        (const float4*)w_kva, (float4*)(wcat_r + Q_LORA),
        HIDDEN, (KV_LORA + ROPE) / 4, NCAT / 4);

    // 1. fused: [q_c_raw | kv_c] = hidden @ w_cat   [2048,2112] K=2048
    mma_gemm<false><<<dim3((NCAT + BNv - 1) / BNv, S / BM, 1), blk, GEMM_SMEM>>>(
        hid_r, HIDDEN, wcat_r, NCAT, qcat, NCAT,
        S, NCAT, HIDDEN, 1.0f);

    // 2. rmsnorm(q_c): qcat[:, :1536] -> qc (rounded)
    rmsnorm_kernel<<<S, blk>>>(qcat, NCAT, qc, Q_LORA, qa_ln_w, Q_LORA);

    // 3. q = q_c @ w_qb                     [2048,3072] K=1536, rounded output
    mma_gemm<true><<<dim3((NH * QK) / BNv, S / BM, 1), blk, GEMM_SMEM>>>(
        qc, Q_LORA, wqb_r, NH * QK, q, NH * QK,
        S, NH * QK, Q_LORA, 1.0f);

    // 4. kv_lat = rmsnorm(qcat[:, 1536:2048]) (rounded)
    rmsnorm_kernel<<<S, blk>>>(qcat + Q_LORA, NCAT, kvlat, KV_LORA, kva_ln_w, KV_LORA);

    // 5. kv = kv_lat @ w_kvb                [2048,4096] K=512, rounded output
    mma_gemm<true><<<dim3((NH * KVD) / BNv, S / BM, 1), blk, GEMM_SMEM>>>(
        kvlat, KV_LORA, wkvb_r, NH * KVD, kv, NH * KVD,
        S, NH * KVD, KV_LORA, 1.0f);

    // 6. RoPE (kv_c block lives at qcat + Q_LORA with ld NCAT)
    rope_kernel<<<S, 512>>>(q, qcat + Q_LORA, NCAT, krope, positions);

    // 7. fused causal flash attention -> attn (tf32-rounded)
    flash_attn_kernel<<<dim3(S / 128, NH), blk, FLASH_SMEM>>>(q, kv, krope, attn);

    // 8. out = attn @ w_o                   [2048,2048] K=2048
    mma_gemm<false><<<dim3(HIDDEN / BNv, S / BM, 1), blk, GEMM_SMEM>>>(
        attn, NH * V_DIM, wo_r, HIDDEN, out, HIDDEN,
        S, HIDDEN, NH * V_DIM, 1.0f);
}